// round 5
// baseline (speedup 1.0000x reference)
#include <cuda_runtime.h>
#include <math.h>

// Problem dims
#define BB   512
#define TT   512
#define IN0  16
#define HH   256
#define NG   1024          // 4*H
#define IN1  (2 * HH)      // 512
#define LOUT 64
#define NBLK 128           // persistent grid: 8 n x 8 m x 2 dirs

// ---------------- device scratch (static, no allocations) ----------------
__device__ float g_out0[(size_t)BB * TT * (2 * HH)];   // layer-0 output [b][t][dir*H+j]
__device__ float g_gx1 [(size_t)2 * TT * BB * NG];     // layer-1 input-GEMM precompute (+bias)
__device__ float g_h0[2][2][BB][HH];                   // [parity][dir][b][j]
__device__ float g_c0[2][BB][HH];
__device__ float g_h1[2][2][BB][HH];
__device__ float g_c1[2][BB][HH];
__device__ unsigned g_arrive;
__device__ unsigned g_gen;

__global__ void zero_kernel()
{
    int tid = blockIdx.x * blockDim.x + threadIdx.x;
    int stride = gridDim.x * blockDim.x;
    for (int i = tid; i < 2 * 2 * BB * HH; i += stride) {
        ((float*)g_h0)[i] = 0.f;
        ((float*)g_h1)[i] = 0.f;
    }
    for (int i = tid; i < 2 * BB * HH; i += stride) {
        ((float*)g_c0)[i] = 0.f;
        ((float*)g_c1)[i] = 0.f;
    }
    if (tid == 0) { g_arrive = 0u; g_gen = 0u; }
}

__device__ __forceinline__ float sigf(float x) { return 1.f / (1.f + __expf(-x)); }

// ---------------- software grid barrier (all NBLK blocks co-resident) ----------------
__device__ __forceinline__ void grid_sync()
{
    __syncthreads();
    if (threadIdx.x == 0) {
        __threadfence();                                  // release this block's writes
        unsigned gen = *(volatile unsigned*)&g_gen;       // read BEFORE arriving
        unsigned a = atomicAdd(&g_arrive, 1u);
        if (a == NBLK - 1) {
            g_arrive = 0u;
            __threadfence();
            atomicAdd(&g_gen, 1u);
        } else {
            while (*(volatile unsigned*)&g_gen == gen) { __nanosleep(64); }
        }
        __threadfence();                                  // acquire (CCTL.IVALL: L1 inval)
    }
    __syncthreads();
}

// Shared tile geometry: BM=64 batch rows x 128 gate cols, 256 threads,
// thread (tx,ty): rows r = ty+16i (i<4), cols c = tx+16j (j<8),
// gate col mapping: n = (c>>5)*HH + n0 + (c&31).
struct SmemU {
    union {
        struct { float As[16][65]; float Ws[16][129]; } s;
        float Gs[64][132];
    };
};

#define GEMM_KK_BODY()                                                     \
    _Pragma("unroll")                                                      \
    for (int kk = 0; kk < 16; kk++) {                                      \
        float a[4], w[8];                                                  \
        _Pragma("unroll") for (int i = 0; i < 4; i++) a[i] = sm.s.As[kk][ty + 16 * i]; \
        _Pragma("unroll") for (int j = 0; j < 8; j++) w[j] = sm.s.Ws[kk][tx + 16 * j]; \
        _Pragma("unroll") for (int i = 0; i < 4; i++)                      \
            _Pragma("unroll") for (int j = 0; j < 8; j++)                  \
                acc[i][j] = fmaf(a[i], w[j], acc[i][j]);                   \
    }

// ---------------- persistent layer-0 kernel (fused input K=16 + recurrent K=256) ----------------
__global__ void __launch_bounds__(256) lstm_seq0(
    const float* __restrict__ x,
    const float* __restrict__ wihf, const float* __restrict__ whhf, const float* __restrict__ bf,
    const float* __restrict__ wihb, const float* __restrict__ whhb, const float* __restrict__ bbias)
{
    const int dir = blockIdx.z;
    const float* wih  = dir ? wihb : wihf;
    const float* whh  = dir ? whhb : whhf;
    const float* bias = dir ? bbias : bf;
    const int n0 = blockIdx.x * 32;
    const int m0 = blockIdx.y * 64;
    const int tid = threadIdx.x, tx = tid & 15, ty = tid >> 4;

    __shared__ SmemU sm;

    for (int t = 0; t < TT; t++) {
        const int tt  = dir ? (TT - 1 - t) : t;
        const int par = t & 1;
        const float* hprev = &g_h0[par][dir][0][0];

        float acc[4][8];
#pragma unroll
        for (int i = 0; i < 4; i++)
#pragma unroll
            for (int j = 0; j < 8; j++) acc[i][j] = 0.f;

        // k-tile 0: input features (K=16 exactly one tile)
        {
#pragma unroll
            for (int i = 0; i < 4; i++) {
                int r = ty + 16 * i;
                sm.s.As[tx][r] = x[((size_t)(m0 + r) * TT + tt) * IN0 + tx];
            }
#pragma unroll
            for (int j = 0; j < 8; j++) {
                int c = ty + 16 * j;
                int n = (c >> 5) * HH + n0 + (c & 31);
                sm.s.Ws[tx][c] = wih[n * IN0 + tx];
            }
            __syncthreads();
            GEMM_KK_BODY();
            __syncthreads();
        }
        // recurrent k-tiles
        for (int k0 = 0; k0 < HH; k0 += 16) {
#pragma unroll
            for (int i = 0; i < 4; i++) {
                int r = ty + 16 * i;
                sm.s.As[tx][r] = hprev[(m0 + r) * HH + k0 + tx];
            }
#pragma unroll
            for (int j = 0; j < 8; j++) {
                int c = ty + 16 * j;
                int n = (c >> 5) * HH + n0 + (c & 31);
                sm.s.Ws[tx][c] = whh[n * HH + k0 + tx];
            }
            __syncthreads();
            GEMM_KK_BODY();
            __syncthreads();
        }

        // bias + stage gates
#pragma unroll
        for (int j = 0; j < 8; j++) {
            int c = tx + 16 * j;
            int n = (c >> 5) * HH + n0 + (c & 31);
            float bv = bias[n];
#pragma unroll
            for (int i = 0; i < 4; i++)
                sm.Gs[ty + 16 * i][c] = acc[i][j] + bv;
        }
        __syncthreads();

        float* cst   = &g_c0[dir][0][0];
        float* hnext = &g_h0[par ^ 1][dir][0][0];
#pragma unroll
        for (int e = 0; e < 8; e++) {
            int p = tid + 256 * e;
            int row = p >> 5, hc = p & 31;
            int b = m0 + row, n = n0 + hc;
            float gi = sm.Gs[row][hc];
            float gf = sm.Gs[row][32 + hc];
            float gg = sm.Gs[row][64 + hc];
            float go = sm.Gs[row][96 + hc];
            float cc = sigf(gf) * cst[b * HH + n] + sigf(gi) * tanhf(gg);
            cst[b * HH + n] = cc;
            float hh = sigf(go) * tanhf(cc);
            hnext[b * HH + n] = hh;
            g_out0[((size_t)b * TT + tt) * (2 * HH) + dir * HH + n] = hh;
        }
        grid_sync();
    }
}

// ---------------- layer-1 input GEMM over all T (fully parallel, +bias) ----------------
__global__ void __launch_bounds__(256) pregemm1(
    const float* __restrict__ wihf, const float* __restrict__ wihb,
    const float* __restrict__ bf,   const float* __restrict__ bbias)
{
    const int z   = blockIdx.z;
    const int dir = z & 1;
    const int t   = z >> 1;
    const float* wih  = dir ? wihb : wihf;
    const float* bias = dir ? bbias : bf;
    const int n0 = blockIdx.x * 32;
    const int m0 = blockIdx.y * 64;
    const int tid = threadIdx.x, tx = tid & 15, ty = tid >> 4;

    __shared__ SmemU sm;

    float acc[4][8];
#pragma unroll
    for (int i = 0; i < 4; i++)
#pragma unroll
        for (int j = 0; j < 8; j++) acc[i][j] = 0.f;

    for (int k0 = 0; k0 < IN1; k0 += 16) {
#pragma unroll
        for (int i = 0; i < 4; i++) {
            int r = ty + 16 * i;
            sm.s.As[tx][r] = g_out0[((size_t)(m0 + r) * TT + t) * IN1 + k0 + tx];
        }
#pragma unroll
        for (int j = 0; j < 8; j++) {
            int c = ty + 16 * j;
            int n = (c >> 5) * HH + n0 + (c & 31);
            sm.s.Ws[tx][c] = wih[n * IN1 + k0 + tx];
        }
        __syncthreads();
        GEMM_KK_BODY();
        __syncthreads();
    }

#pragma unroll
    for (int j = 0; j < 8; j++) {
        int c = tx + 16 * j;
        int n = (c >> 5) * HH + n0 + (c & 31);
        float bv = bias[n];
#pragma unroll
        for (int i = 0; i < 4; i++) {
            int r = ty + 16 * i;
            g_gx1[((size_t)(dir * TT + t) * BB + m0 + r) * NG + n] = acc[i][j] + bv;
        }
    }
}

// ---------------- persistent layer-1 recurrent kernel (K=256, gx preloaded) ----------------
__global__ void __launch_bounds__(256) lstm_seq1(
    const float* __restrict__ whhf, const float* __restrict__ whhb)
{
    const int dir = blockIdx.z;
    const float* whh = dir ? whhb : whhf;
    const int n0 = blockIdx.x * 32;
    const int m0 = blockIdx.y * 64;
    const int tid = threadIdx.x, tx = tid & 15, ty = tid >> 4;

    __shared__ SmemU sm;

    for (int t = 0; t < TT; t++) {
        const int tt  = dir ? (TT - 1 - t) : t;
        const int par = t & 1;
        const float* hprev = &g_h1[par][dir][0][0];

        float acc[4][8];
#pragma unroll
        for (int i = 0; i < 4; i++)
#pragma unroll
            for (int j = 0; j < 8; j++) acc[i][j] = 0.f;

        for (int k0 = 0; k0 < HH; k0 += 16) {
#pragma unroll
            for (int i = 0; i < 4; i++) {
                int r = ty + 16 * i;
                sm.s.As[tx][r] = hprev[(m0 + r) * HH + k0 + tx];
            }
#pragma unroll
            for (int j = 0; j < 8; j++) {
                int c = ty + 16 * j;
                int n = (c >> 5) * HH + n0 + (c & 31);
                sm.s.Ws[tx][c] = whh[n * HH + k0 + tx];
            }
            __syncthreads();
            GEMM_KK_BODY();
            __syncthreads();
        }

        // add precomputed input-GEMM (+bias) and stage gates
#pragma unroll
        for (int j = 0; j < 8; j++) {
            int c = tx + 16 * j;
            int n = (c >> 5) * HH + n0 + (c & 31);
#pragma unroll
            for (int i = 0; i < 4; i++) {
                int r = ty + 16 * i;
                float gx = g_gx1[((size_t)(dir * TT + tt) * BB + m0 + r) * NG + n];
                sm.Gs[r][c] = acc[i][j] + gx;
            }
        }
        __syncthreads();

        float* cst   = &g_c1[dir][0][0];
        float* hnext = &g_h1[par ^ 1][dir][0][0];
#pragma unroll
        for (int e = 0; e < 8; e++) {
            int p = tid + 256 * e;
            int row = p >> 5, hc = p & 31;
            int b = m0 + row, n = n0 + hc;
            float gi = sm.Gs[row][hc];
            float gf = sm.Gs[row][32 + hc];
            float gg = sm.Gs[row][64 + hc];
            float go = sm.Gs[row][96 + hc];
            float cc = sigf(gf) * cst[b * HH + n] + sigf(gi) * tanhf(gg);
            cst[b * HH + n] = cc;
            hnext[b * HH + n] = sigf(go) * tanhf(cc);
        }
        grid_sync();
    }
}

// ---------------- final projection ----------------
__global__ void fc_kernel(const float* __restrict__ fcw, const float* __restrict__ fcb,
                          float* __restrict__ out)
{
    int b = blockIdx.x;
    int l = threadIdx.x;   // 64 threads
    __shared__ float hs[2 * HH];
    for (int j = threadIdx.x; j < 2 * HH; j += blockDim.x)
        hs[j] = (j < HH) ? g_h1[0][0][b][j] : g_h1[0][1][b][j - HH];
    __syncthreads();
    float s = fcb[l];
#pragma unroll 8
    for (int j = 0; j < 2 * HH; j++)
        s = fmaf(hs[j], fcw[l * (2 * HH) + j], s);
    out[b * LOUT + l] = s;
}

// ---------------- launch ----------------
extern "C" void kernel_launch(void* const* d_in, const int* in_sizes, int n_in,
                              void* d_out, int out_size)
{
    const float* x     = (const float*)d_in[0];
    const float* wih0f = (const float*)d_in[1];
    const float* whh0f = (const float*)d_in[2];
    const float* b0f   = (const float*)d_in[3];
    const float* wih0b = (const float*)d_in[4];
    const float* whh0b = (const float*)d_in[5];
    const float* b0b   = (const float*)d_in[6];
    const float* wih1f = (const float*)d_in[7];
    const float* whh1f = (const float*)d_in[8];
    const float* b1f   = (const float*)d_in[9];
    const float* wih1b = (const float*)d_in[10];
    const float* whh1b = (const float*)d_in[11];
    const float* b1b   = (const float*)d_in[12];
    const float* fcw   = (const float*)d_in[13];
    const float* fcb   = (const float*)d_in[14];
    float* out = (float*)d_out;

    zero_kernel<<<256, 256>>>();

    dim3 g8(8, 8, 2);
    lstm_seq0<<<g8, 256>>>(x, wih0f, whh0f, b0f, wih0b, whh0b, b0b);

    dim3 gp(8, 8, TT * 2);
    pregemm1<<<gp, 256>>>(wih1f, wih1b, b1f, b1b);

    lstm_seq1<<<g8, 256>>>(whh1f, whh1b);

    fc_kernel<<<BB, LOUT>>>(fcw, fcb, out);
}

// round 7
// speedup vs baseline: 1.3064x; 1.3064x over previous
#include <cuda_runtime.h>
#include <cuda_bf16.h>
#include <cstdint>
#include <math.h>

// Problem dims
#define BB   512
#define TT   512
#define IN0  16
#define HH   256
#define NG   1024          // 4*H
#define IN1  (2 * HH)      // 512
#define LOUT 64
#define NBLK 128           // persistent grid: 8 n x 8 m x 2 dirs

// ---------------- device scratch (static, no allocations) ----------------
__device__ float g_out0[(size_t)BB * TT * IN1];        // layer-0 output [b][t][dir*H+j]
__device__ float g_gx1 [(size_t)2 * TT * BB * NG];     // layer-1 input-GEMM precompute (+bias)
__device__ __nv_bfloat16 g_x1h[(size_t)BB * TT * IN1]; // split-bf16 hi of x1
__device__ __nv_bfloat16 g_x1l[(size_t)BB * TT * IN1]; // split-bf16 lo of x1
__device__ __nv_bfloat16 g_w1h[2][NG][IN1];            // split-bf16 hi of w_ih1
__device__ __nv_bfloat16 g_w1l[2][NG][IN1];            // split-bf16 lo of w_ih1
__device__ float g_h0[2][2][BB][HH];                   // [parity][dir][b][j]
__device__ float g_c0[2][BB][HH];
__device__ float g_h1[2][2][BB][HH];
__device__ float g_c1[2][BB][HH];
__device__ unsigned g_arrive;
__device__ unsigned g_gen;

__global__ void zero_kernel()
{
    int tid = blockIdx.x * blockDim.x + threadIdx.x;
    int stride = gridDim.x * blockDim.x;
    for (int i = tid; i < 2 * 2 * BB * HH; i += stride) {
        ((float*)g_h0)[i] = 0.f;
        ((float*)g_h1)[i] = 0.f;
    }
    for (int i = tid; i < 2 * BB * HH; i += stride) {
        ((float*)g_c0)[i] = 0.f;
        ((float*)g_c1)[i] = 0.f;
    }
    if (tid == 0) { g_arrive = 0u; g_gen = 0u; }
}

__device__ __forceinline__ float sigf(float x) { return 1.f / (1.f + __expf(-x)); }

// ---------------- software grid barrier (all NBLK blocks co-resident) ----------------
__device__ __forceinline__ void grid_sync()
{
    __syncthreads();
    if (threadIdx.x == 0) {
        __threadfence();
        unsigned gen = *(volatile unsigned*)&g_gen;
        unsigned a = atomicAdd(&g_arrive, 1u);
        if (a == NBLK - 1) {
            g_arrive = 0u;
            __threadfence();
            atomicAdd(&g_gen, 1u);
        } else {
            while (*(volatile unsigned*)&g_gen == gen) { __nanosleep(64); }
        }
        __threadfence();
    }
    __syncthreads();
}

// ======================= helpers =======================
__device__ __forceinline__ uint32_t smem_u32(const void* p) {
    uint32_t a;
    asm("{ .reg .u64 t; cvta.to.shared.u64 t, %1; cvt.u32.u64 %0, t; }" : "=r"(a) : "l"(p));
    return a;
}
#define CP_ASYNC16(dst, src) \
    asm volatile("cp.async.cg.shared.global [%0], [%1], 16;" :: "r"(dst), "l"(src) : "memory")
#define CP_COMMIT() asm volatile("cp.async.commit_group;" ::: "memory")
#define CP_WAIT1()  asm volatile("cp.async.wait_group 1;" ::: "memory")
#define CP_WAIT0()  asm volatile("cp.async.wait_group 0;" ::: "memory")
#define LDMATRIX_X4(r0, r1, r2, r3, addr) \
    asm volatile("ldmatrix.sync.aligned.m8n8.x4.shared.b16 {%0,%1,%2,%3}, [%4];" \
                 : "=r"(r0), "=r"(r1), "=r"(r2), "=r"(r3) : "r"(addr))
#define MMA_BF16(c0, c1, c2, c3, a0, a1, a2, a3, b0, b1) \
    asm volatile("mma.sync.aligned.m16n8k16.row.col.f32.bf16.bf16.f32 " \
                 "{%0,%1,%2,%3}, {%4,%5,%6,%7}, {%8,%9}, {%0,%1,%2,%3};" \
                 : "+f"(c0), "+f"(c1), "+f"(c2), "+f"(c3) \
                 : "r"(a0), "r"(a1), "r"(a2), "r"(a3), "r"(b0), "r"(b1))

// ======================= split-bf16 conversion kernels =======================
__global__ void conv_x1_kernel()
{
    size_t n4 = (size_t)BB * TT * IN1 / 4;
    size_t i = (size_t)blockIdx.x * blockDim.x + threadIdx.x;
    size_t stride = (size_t)gridDim.x * blockDim.x;
    for (; i < n4; i += stride) {
        float4 v = ((const float4*)g_out0)[i];
        float f[4] = {v.x, v.y, v.z, v.w};
        union { __nv_bfloat16 h[4]; uint2 u; } H, L;
#pragma unroll
        for (int j = 0; j < 4; j++) {
            H.h[j] = __float2bfloat16(f[j]);
            L.h[j] = __float2bfloat16(f[j] - __bfloat162float(H.h[j]));
        }
        ((uint2*)g_x1h)[i] = H.u;
        ((uint2*)g_x1l)[i] = L.u;
    }
}

__global__ void conv_w1_kernel(const float* __restrict__ wf, const float* __restrict__ wb)
{
    const int n = NG * IN1;
    int i = blockIdx.x * blockDim.x + threadIdx.x;
    int stride = gridDim.x * blockDim.x;
    for (; i < 2 * n; i += stride) {
        int d = i / n, r = i % n;
        float v = (d ? wb : wf)[r];
        __nv_bfloat16 h = __float2bfloat16(v);
        ((__nv_bfloat16*)g_w1h)[i] = h;
        ((__nv_bfloat16*)g_w1l)[i] = __float2bfloat16(v - __bfloat162float(h));
    }
}

// ======================= mma.sync layer-1 input pre-GEMM =======================
// C[(b,t), n] = x1 . w_ih1^T + bias, split-bf16 (3 passes: hh + lh + hl), fp32 acc.
// CTA tile: 128 rows x 128 gate cols. BK=32, 2-stage cp.async pipeline.
// 8 warps in 2(m) x 4(n); warp tile 64x32 = 4 m16 x 4 n8.
// Smem row pad: 32->40 bf16 (80B): ldmatrix row addrs hit all 32 banks once.
#define PG_PAD    40
#define PG_HBYTES (128 * PG_PAD * 2)           // one [128][40] bf16 plane: 10240B
#define PG_SMEM   (2 * 2 * PG_HBYTES * 2)      // A + W, 2 stages, hi/lo: 81920B

__device__ __forceinline__ void pg_load_stage(
    uint32_t sA, uint32_t sW,
    const __nv_bfloat16* Ah, const __nv_bfloat16* Al,
    const __nv_bfloat16* Wh, const __nv_bfloat16* Wl,
    int k0, int tid)
{
#pragma unroll
    for (int i = 0; i < 2; i++) {
        int chunk = tid + 256 * i;          // 512 chunks per plane
        int row = chunk >> 2, seg = chunk & 3;
        uint32_t doff = (uint32_t)(row * (PG_PAD * 2) + seg * 16);
        const char* a_h = (const char*)(Ah + (size_t)row * IN1 + k0) + seg * 16;
        const char* a_l = (const char*)(Al + (size_t)row * IN1 + k0) + seg * 16;
        const char* w_h = (const char*)(Wh + (size_t)row * IN1 + k0) + seg * 16;
        const char* w_l = (const char*)(Wl + (size_t)row * IN1 + k0) + seg * 16;
        CP_ASYNC16(sA + doff, a_h);
        CP_ASYNC16(sA + PG_HBYTES + doff, a_l);
        CP_ASYNC16(sW + doff, w_h);
        CP_ASYNC16(sW + PG_HBYTES + doff, w_l);
    }
}

__global__ void __launch_bounds__(256, 1) pregemm_mma(
    const float* __restrict__ b1f, const float* __restrict__ b1b)
{
    extern __shared__ char smem[];
    __shared__ float bias_s[128];
    const uint32_t sA0 = smem_u32(smem);                 // [stage][hi/lo][128][40]
    const uint32_t sW0 = sA0 + 2 * 2 * PG_HBYTES;
    const int tid = threadIdx.x;
    const int wid = tid >> 5, lid = tid & 31;
    const int warp_m = wid >> 2, warp_n = wid & 3;

    const int dir   = blockIdx.x >> 3;
    const int ntile = blockIdx.x & 7;      // 8 x 128 gate cols
    const int mtile = blockIdx.y;          // 2048 x 128 rows

    const float* bsrc = dir ? b1b : b1f;
    if (tid < 128) bias_s[tid] = bsrc[ntile * 128 + tid];

    const __nv_bfloat16* Ah = g_x1h + (size_t)mtile * 128 * IN1;
    const __nv_bfloat16* Al = g_x1l + (size_t)mtile * 128 * IN1;
    const __nv_bfloat16* Wh = &g_w1h[dir][ntile * 128][0];
    const __nv_bfloat16* Wl = &g_w1l[dir][ntile * 128][0];

    float c[4][4][4];
#pragma unroll
    for (int mt = 0; mt < 4; mt++)
#pragma unroll
        for (int nt = 0; nt < 4; nt++)
#pragma unroll
            for (int r = 0; r < 4; r++) c[mt][nt][r] = 0.f;

    // prologue
    pg_load_stage(sA0, sW0, Ah, Al, Wh, Wl, 0, tid);  CP_COMMIT();
    pg_load_stage(sA0 + 2 * PG_HBYTES, sW0 + 2 * PG_HBYTES, Ah, Al, Wh, Wl, 32, tid); CP_COMMIT();

    // ldmatrix lane-address components
    const int a_row = (lid & 15);
    const int a_kof = (lid >> 4) * 8;
    const int b_g   = lid >> 3;
    const int b_row = (b_g >> 1) * 8 + (lid & 7);
    const int b_kof = (b_g & 1) * 8;

    for (int ci = 0; ci < 16; ci++) {
        const int st = ci & 1;
        if (ci == 15) CP_WAIT0(); else CP_WAIT1();
        __syncthreads();

        const uint32_t sA = sA0 + st * 2 * PG_HBYTES;
        const uint32_t sW = sW0 + st * 2 * PG_HBYTES;

#pragma unroll
        for (int ks = 0; ks < 32; ks += 16) {
            uint32_t aH[4][4], aL[4][4], bH[2][4], bL[2][4];
#pragma unroll
            for (int mt = 0; mt < 4; mt++) {
                int row = warp_m * 64 + mt * 16 + a_row;
                uint32_t off = (uint32_t)(row * (PG_PAD * 2) + (ks + a_kof) * 2);
                LDMATRIX_X4(aH[mt][0], aH[mt][1], aH[mt][2], aH[mt][3], sA + off);
                LDMATRIX_X4(aL[mt][0], aL[mt][1], aL[mt][2], aL[mt][3], sA + PG_HBYTES + off);
            }
#pragma unroll
            for (int bt = 0; bt < 2; bt++) {
                int row = warp_n * 32 + bt * 16 + b_row;
                uint32_t off = (uint32_t)(row * (PG_PAD * 2) + (ks + b_kof) * 2);
                LDMATRIX_X4(bH[bt][0], bH[bt][1], bH[bt][2], bH[bt][3], sW + off);
                LDMATRIX_X4(bL[bt][0], bL[bt][1], bL[bt][2], bL[bt][3], sW + PG_HBYTES + off);
            }
#pragma unroll
            for (int mt = 0; mt < 4; mt++)
#pragma unroll
                for (int nt = 0; nt < 4; nt++) {
                    int bt = nt >> 1, sub = (nt & 1) * 2;
                    // hi*hi
                    MMA_BF16(c[mt][nt][0], c[mt][nt][1], c[mt][nt][2], c[mt][nt][3],
                             aH[mt][0], aH[mt][1], aH[mt][2], aH[mt][3],
                             bH[bt][sub], bH[bt][sub + 1]);
                    // lo*hi
                    MMA_BF16(c[mt][nt][0], c[mt][nt][1], c[mt][nt][2], c[mt][nt][3],
                             aL[mt][0], aL[mt][1], aL[mt][2], aL[mt][3],
                             bH[bt][sub], bH[bt][sub + 1]);
                    // hi*lo
                    MMA_BF16(c[mt][nt][0], c[mt][nt][1], c[mt][nt][2], c[mt][nt][3],
                             aH[mt][0], aH[mt][1], aH[mt][2], aH[mt][3],
                             bL[bt][sub], bL[bt][sub + 1]);
                }
        }
        __syncthreads();
        if (ci + 2 < 16) {
            pg_load_stage(sA, sW, Ah, Al, Wh, Wl, (ci + 2) * 32, tid);
            CP_COMMIT();
        }
    }

    // epilogue: c -> g_gx1 with bias (gx1 layout: [dir][t][b][n])
#pragma unroll
    for (int mt = 0; mt < 4; mt++) {
#pragma unroll
        for (int rh = 0; rh < 2; rh++) {
            int row = warp_m * 64 + mt * 16 + (lid >> 2) + rh * 8;
            size_t R = (size_t)mtile * 128 + row;     // = b*TT + t
            int b = (int)(R >> 9), t = (int)(R & 511);
            float* dst = g_gx1 + (((size_t)dir * TT + t) * BB + b) * NG + ntile * 128;
#pragma unroll
            for (int nt = 0; nt < 4; nt++) {
                int col = warp_n * 32 + nt * 8 + (lid & 3) * 2;
                float2 v;
                v.x = c[mt][nt][rh * 2 + 0] + bias_s[col];
                v.y = c[mt][nt][rh * 2 + 1] + bias_s[col + 1];
                *(float2*)(dst + col) = v;
            }
        }
    }
}

// ======================= SIMT pieces (unchanged, passing) =======================
struct SmemU {
    union {
        struct { float As[16][65]; float Ws[16][129]; } s;
        float Gs[64][132];
    };
};

#define GEMM_KK_BODY()                                                     \
    _Pragma("unroll")                                                      \
    for (int kk = 0; kk < 16; kk++) {                                      \
        float a[4], w[8];                                                  \
        _Pragma("unroll") for (int i = 0; i < 4; i++) a[i] = sm.s.As[kk][ty + 16 * i]; \
        _Pragma("unroll") for (int j = 0; j < 8; j++) w[j] = sm.s.Ws[kk][tx + 16 * j]; \
        _Pragma("unroll") for (int i = 0; i < 4; i++)                      \
            _Pragma("unroll") for (int j = 0; j < 8; j++)                  \
                acc[i][j] = fmaf(a[i], w[j], acc[i][j]);                   \
    }

__global__ void __launch_bounds__(256) lstm_seq0(
    const float* __restrict__ x,
    const float* __restrict__ wihf, const float* __restrict__ whhf, const float* __restrict__ bf,
    const float* __restrict__ wihb, const float* __restrict__ whhb, const float* __restrict__ bbias)
{
    const int dir = blockIdx.z;
    const float* wih  = dir ? wihb : wihf;
    const float* whh  = dir ? whhb : whhf;
    const float* bias = dir ? bbias : bf;
    const int n0 = blockIdx.x * 32;
    const int m0 = blockIdx.y * 64;
    const int tid = threadIdx.x, tx = tid & 15, ty = tid >> 4;

    __shared__ SmemU sm;

    for (int t = 0; t < TT; t++) {
        const int tt  = dir ? (TT - 1 - t) : t;
        const int par = t & 1;
        const float* hprev = &g_h0[par][dir][0][0];

        float acc[4][8];
#pragma unroll
        for (int i = 0; i < 4; i++)
#pragma unroll
            for (int j = 0; j < 8; j++) acc[i][j] = 0.f;

        {
#pragma unroll
            for (int i = 0; i < 4; i++) {
                int r = ty + 16 * i;
                sm.s.As[tx][r] = x[((size_t)(m0 + r) * TT + tt) * IN0 + tx];
            }
#pragma unroll
            for (int j = 0; j < 8; j++) {
                int c = ty + 16 * j;
                int n = (c >> 5) * HH + n0 + (c & 31);
                sm.s.Ws[tx][c] = wih[n * IN0 + tx];
            }
            __syncthreads();
            GEMM_KK_BODY();
            __syncthreads();
        }
        for (int k0 = 0; k0 < HH; k0 += 16) {
#pragma unroll
            for (int i = 0; i < 4; i++) {
                int r = ty + 16 * i;
                sm.s.As[tx][r] = hprev[(m0 + r) * HH + k0 + tx];
            }
#pragma unroll
            for (int j = 0; j < 8; j++) {
                int c = ty + 16 * j;
                int n = (c >> 5) * HH + n0 + (c & 31);
                sm.s.Ws[tx][c] = whh[n * HH + k0 + tx];
            }
            __syncthreads();
            GEMM_KK_BODY();
            __syncthreads();
        }

#pragma unroll
        for (int j = 0; j < 8; j++) {
            int c = tx + 16 * j;
            int n = (c >> 5) * HH + n0 + (c & 31);
            float bv = bias[n];
#pragma unroll
            for (int i = 0; i < 4; i++)
                sm.Gs[ty + 16 * i][c] = acc[i][j] + bv;
        }
        __syncthreads();

        float* cst   = &g_c0[dir][0][0];
        float* hnext = &g_h0[par ^ 1][dir][0][0];
#pragma unroll
        for (int e = 0; e < 8; e++) {
            int p = tid + 256 * e;
            int row = p >> 5, hc = p & 31;
            int b = m0 + row, n = n0 + hc;
            float gi = sm.Gs[row][hc];
            float gf = sm.Gs[row][32 + hc];
            float gg = sm.Gs[row][64 + hc];
            float go = sm.Gs[row][96 + hc];
            float cc = sigf(gf) * cst[b * HH + n] + sigf(gi) * tanhf(gg);
            cst[b * HH + n] = cc;
            float hh = sigf(go) * tanhf(cc);
            hnext[b * HH + n] = hh;
            g_out0[((size_t)b * TT + tt) * (2 * HH) + dir * HH + n] = hh;
        }
        grid_sync();
    }
}

__global__ void __launch_bounds__(256) lstm_seq1(
    const float* __restrict__ whhf, const float* __restrict__ whhb)
{
    const int dir = blockIdx.z;
    const float* whh = dir ? whhb : whhf;
    const int n0 = blockIdx.x * 32;
    const int m0 = blockIdx.y * 64;
    const int tid = threadIdx.x, tx = tid & 15, ty = tid >> 4;

    __shared__ SmemU sm;

    for (int t = 0; t < TT; t++) {
        const int tt  = dir ? (TT - 1 - t) : t;
        const int par = t & 1;
        const float* hprev = &g_h1[par][dir][0][0];

        float acc[4][8];
#pragma unroll
        for (int i = 0; i < 4; i++)
#pragma unroll
            for (int j = 0; j < 8; j++) acc[i][j] = 0.f;

        for (int k0 = 0; k0 < HH; k0 += 16) {
#pragma unroll
            for (int i = 0; i < 4; i++) {
                int r = ty + 16 * i;
                sm.s.As[tx][r] = hprev[(m0 + r) * HH + k0 + tx];
            }
#pragma unroll
            for (int j = 0; j < 8; j++) {
                int c = ty + 16 * j;
                int n = (c >> 5) * HH + n0 + (c & 31);
                sm.s.Ws[tx][c] = whh[n * HH + k0 + tx];
            }
            __syncthreads();
            GEMM_KK_BODY();
            __syncthreads();
        }

#pragma unroll
        for (int j = 0; j < 8; j++) {
            int c = tx + 16 * j;
            int n = (c >> 5) * HH + n0 + (c & 31);
#pragma unroll
            for (int i = 0; i < 4; i++) {
                int r = ty + 16 * i;
                float gx = g_gx1[((size_t)(dir * TT + tt) * BB + m0 + r) * NG + n];
                sm.Gs[r][c] = acc[i][j] + gx;
            }
        }
        __syncthreads();

        float* cst   = &g_c1[dir][0][0];
        float* hnext = &g_h1[par ^ 1][dir][0][0];
#pragma unroll
        for (int e = 0; e < 8; e++) {
            int p = tid + 256 * e;
            int row = p >> 5, hc = p & 31;
            int b = m0 + row, n = n0 + hc;
            float gi = sm.Gs[row][hc];
            float gf = sm.Gs[row][32 + hc];
            float gg = sm.Gs[row][64 + hc];
            float go = sm.Gs[row][96 + hc];
            float cc = sigf(gf) * cst[b * HH + n] + sigf(gi) * tanhf(gg);
            cst[b * HH + n] = cc;
            hnext[b * HH + n] = sigf(go) * tanhf(cc);
        }
        grid_sync();
    }
}

__global__ void fc_kernel(const float* __restrict__ fcw, const float* __restrict__ fcb,
                          float* __restrict__ out)
{
    int b = blockIdx.x;
    int l = threadIdx.x;   // 64 threads
    __shared__ float hs[2 * HH];
    for (int j = threadIdx.x; j < 2 * HH; j += blockDim.x)
        hs[j] = (j < HH) ? g_h1[0][0][b][j] : g_h1[0][1][b][j - HH];
    __syncthreads();
    float s = fcb[l];
#pragma unroll 8
    for (int j = 0; j < 2 * HH; j++)
        s = fmaf(hs[j], fcw[l * (2 * HH) + j], s);
    out[b * LOUT + l] = s;
}

// ---------------- launch ----------------
extern "C" void kernel_launch(void* const* d_in, const int* in_sizes, int n_in,
                              void* d_out, int out_size)
{
    const float* x     = (const float*)d_in[0];
    const float* wih0f = (const float*)d_in[1];
    const float* whh0f = (const float*)d_in[2];
    const float* b0f   = (const float*)d_in[3];
    const float* wih0b = (const float*)d_in[4];
    const float* whh0b = (const float*)d_in[5];
    const float* b0b   = (const float*)d_in[6];
    const float* wih1f = (const float*)d_in[7];
    const float* whh1f = (const float*)d_in[8];
    const float* b1f   = (const float*)d_in[9];
    const float* wih1b = (const float*)d_in[10];
    const float* whh1b = (const float*)d_in[11];
    const float* b1b   = (const float*)d_in[12];
    const float* fcw   = (const float*)d_in[13];
    const float* fcb   = (const float*)d_in[14];
    float* out = (float*)d_out;

    cudaFuncSetAttribute(pregemm_mma, cudaFuncAttributeMaxDynamicSharedMemorySize, PG_SMEM);

    zero_kernel<<<256, 256>>>();
    conv_w1_kernel<<<512, 256>>>(wih1f, wih1b);

    dim3 g8(8, 8, 2);
    lstm_seq0<<<g8, 256>>>(x, wih0f, whh0f, b0f, wih0b, whh0b, b0b);

    conv_x1_kernel<<<2048, 256>>>();

    dim3 gt(16, 2048, 1);   // (dir*8 + ntile) x mtile
    pregemm_mma<<<gt, 256, PG_SMEM>>>(b1f, b1b);

    lstm_seq1<<<g8, 256>>>(whh1f, whh1b);

    fc_kernel<<<BB, LOUT>>>(fcw, fcb, out);
}

// round 8
// speedup vs baseline: 2.5105x; 1.9217x over previous
#include <cuda_runtime.h>
#include <cuda_bf16.h>
#include <cstdint>
#include <math.h>

// Problem dims
#define BB   512
#define TT   512
#define IN0  16
#define HH   256
#define NG   1024          // 4*H
#define IN1  (2 * HH)      // 512
#define LOUT 64

// ---------------- device scratch (static, no allocations) ----------------
__device__ float g_gx1 [(size_t)2 * TT * BB * NG];     // layer-1 input-GEMM precompute (+bias)
__device__ __nv_bfloat16 g_x1h[(size_t)BB * TT * IN1]; // split-bf16 hi of x1 (layer-0 output)
__device__ __nv_bfloat16 g_x1l[(size_t)BB * TT * IN1];
__device__ __nv_bfloat16 g_w1h[2][NG][IN1];            // split-bf16 of w_ih1
__device__ __nv_bfloat16 g_w1l[2][NG][IN1];
__device__ __nv_bfloat16 g_x0h[(size_t)BB * TT * IN0]; // split-bf16 of x
__device__ __nv_bfloat16 g_x0l[(size_t)BB * TT * IN0];
__device__ __nv_bfloat16 g_w0h[2][NG][IN0];            // split-bf16 of w_ih0
__device__ __nv_bfloat16 g_w0l[2][NG][IN0];
__device__ __nv_bfloat16 g_whh_h[2][2][NG][HH];        // [layer][dir]
__device__ __nv_bfloat16 g_whh_l[2][2][NG][HH];
__device__ __nv_bfloat16 g_hh[2][2][2][BB][HH];        // [layer][parity][dir][b][j]
__device__ __nv_bfloat16 g_hl[2][2][2][BB][HH];
__device__ unsigned g_garr[2][16];
__device__ unsigned g_ggen[2][16];

__global__ void zero_kernel()
{
    int tid = blockIdx.x * blockDim.x + threadIdx.x;
    int stride = gridDim.x * blockDim.x;
    const int nh = 2 * 2 * 2 * BB * HH / 2;   // uint count per array
    for (int i = tid; i < nh; i += stride) {
        ((unsigned*)g_hh)[i] = 0u;
        ((unsigned*)g_hl)[i] = 0u;
    }
    if (tid < 32) {
        ((unsigned*)g_garr)[tid] = 0u;
        ((unsigned*)g_ggen)[tid] = 0u;
    }
}

__device__ __forceinline__ float sigf(float x) { return 1.f / (1.f + __expf(-x)); }
__device__ __forceinline__ float tanhf_fast(float x) { return 2.f / (1.f + __expf(-2.f * x)) - 1.f; }

// ======================= helpers =======================
__device__ __forceinline__ uint32_t smem_u32(const void* p) {
    uint32_t a;
    asm("{ .reg .u64 t; cvta.to.shared.u64 t, %1; cvt.u32.u64 %0, t; }" : "=r"(a) : "l"(p));
    return a;
}
#define CP_ASYNC16(dst, src) \
    asm volatile("cp.async.cg.shared.global [%0], [%1], 16;" :: "r"(dst), "l"(src) : "memory")
#define CP_COMMIT() asm volatile("cp.async.commit_group;" ::: "memory")
#define CP_WAIT1()  asm volatile("cp.async.wait_group 1;" ::: "memory")
#define CP_WAIT0()  asm volatile("cp.async.wait_group 0;" ::: "memory")
#define LDMATRIX_X4(r0, r1, r2, r3, addr) \
    asm volatile("ldmatrix.sync.aligned.m8n8.x4.shared.b16 {%0,%1,%2,%3}, [%4];" \
                 : "=r"(r0), "=r"(r1), "=r"(r2), "=r"(r3) : "r"(addr))
#define MMA_BF16(c0, c1, c2, c3, a0, a1, a2, a3, b0, b1) \
    asm volatile("mma.sync.aligned.m16n8k16.row.col.f32.bf16.bf16.f32 " \
                 "{%0,%1,%2,%3}, {%4,%5,%6,%7}, {%8,%9}, {%0,%1,%2,%3};" \
                 : "+f"(c0), "+f"(c1), "+f"(c2), "+f"(c3) \
                 : "r"(a0), "r"(a1), "r"(a2), "r"(a3), "r"(b0), "r"(b1))

// ---------------- per-group (8-block) barrier ----------------
__device__ __forceinline__ void group_sync(unsigned* arr, unsigned* gen)
{
    __syncthreads();
    if (threadIdx.x == 0) {
        __threadfence();
        unsigned g = *(volatile unsigned*)gen;
        if (atomicAdd(arr, 1u) == 7u) {
            atomicExch(arr, 0u);
            __threadfence();
            atomicAdd(gen, 1u);
        } else {
            while (*(volatile unsigned*)gen == g) { __nanosleep(32); }
        }
        __threadfence();
    }
    __syncthreads();
}

// ======================= split-bf16 conversion =======================
__global__ void split_kernel(const float* __restrict__ src,
                             __nv_bfloat16* __restrict__ dh,
                             __nv_bfloat16* __restrict__ dl, int n)
{
    int i = blockIdx.x * blockDim.x + threadIdx.x;
    int stride = gridDim.x * blockDim.x;
    for (; i < n; i += stride) {
        float v = src[i];
        __nv_bfloat16 h = __float2bfloat16(v);
        dh[i] = h;
        dl[i] = __float2bfloat16(v - __bfloat162float(h));
    }
}

__global__ void conv_w1_kernel(const float* __restrict__ wf, const float* __restrict__ wb)
{
    const int n = NG * IN1;
    int i = blockIdx.x * blockDim.x + threadIdx.x;
    int stride = gridDim.x * blockDim.x;
    for (; i < 2 * n; i += stride) {
        int d = i / n, r = i % n;
        float v = (d ? wb : wf)[r];
        __nv_bfloat16 h = __float2bfloat16(v);
        ((__nv_bfloat16*)g_w1h)[i] = h;
        ((__nv_bfloat16*)g_w1l)[i] = __float2bfloat16(v - __bfloat162float(h));
    }
}

// ======================= tensorized persistent LSTM layer =======================
// KIN = 16 (layer 0, x fused into K) or 0 (layer 1, gx1 precomputed).
// Block: 256 thr (8 warps: 2m x 4gate). Tile: 64 batch rows x 32 h-cols x 4 gates.
// W tile (split bf16) resident in smem for all 512 steps. c-state in registers.
template<int KIN>
__global__ void __launch_bounds__(256, 1) lstm_seq_tc(
    const float* __restrict__ bias_f, const float* __restrict__ bias_b)
{
    constexpr int LAYER = (KIN == 16) ? 0 : 1;
    constexpr int K     = KIN + HH;          // 272 / 256
    constexpr int KS    = K / 16;            // 17 / 16
    constexpr int SEGW  = K / 8;             // 16B segs per row: 34 / 32
    constexpr int XSEG  = KIN / 8;           // 2 / 0
    constexpr int ROWB  = (K + 8) * 2;       // padded row bytes: 560 / 528 (conflict-free)

    extern __shared__ char smem[];
    const uint32_t sA_h = smem_u32(smem);
    const uint32_t sA_l = sA_h + 64 * ROWB;
    const uint32_t sW_h = sA_l + 64 * ROWB;
    const uint32_t sW_l = sW_h + 128 * ROWB;
    float* Gs = (float*)smem;                // aliases A planes (reloaded each step)
    __shared__ float bias_s[128];

    const int tid = threadIdx.x;
    const int wid = tid >> 5, lid = tid & 31;
    const int warp_m = wid >> 2, warp_n = wid & 3;   // warp_n = gate
    const int bx = blockIdx.x;
    const int n_idx = bx & 7, m_idx = (bx >> 3) & 7, dir = bx >> 6;
    const int n0 = n_idx * 32, m0 = m_idx * 64;
    unsigned* barr = &g_garr[LAYER][dir * 8 + m_idx];
    unsigned* bgen = &g_ggen[LAYER][dir * 8 + m_idx];

    if (LAYER == 0 && tid < 128)
        bias_s[tid] = (dir ? bias_b : bias_f)[(tid >> 5) * 256 + n0 + (tid & 31)];

    // ---- preload W tile (rows r = gate*32 + j -> n = gate*256 + n0 + j) ----
    {
        const __nv_bfloat16* wh = &g_whh_h[LAYER][dir][0][0];
        const __nv_bfloat16* wl = &g_whh_l[LAYER][dir][0][0];
        for (int s = tid; s < 128 * SEGW; s += 256) {
            int r = s / SEGW, seg = s % SEGW;
            int n = (r >> 5) * 256 + n0 + (r & 31);
            uint32_t dst = (uint32_t)(r * ROWB + seg * 16);
            if (KIN == 16 && seg < XSEG) {
                CP_ASYNC16(sW_h + dst, (const char*)&g_w0h[dir][n][seg * 8]);
                CP_ASYNC16(sW_l + dst, (const char*)&g_w0l[dir][n][seg * 8]);
            } else {
                int hs = seg - XSEG;
                CP_ASYNC16(sW_h + dst, (const char*)&wh[n * HH + hs * 8]);
                CP_ASYNC16(sW_l + dst, (const char*)&wl[n * HH + hs * 8]);
            }
        }
        CP_COMMIT(); CP_WAIT0();
        __syncthreads();
    }

    float cstate[8];
#pragma unroll
    for (int e = 0; e < 8; e++) cstate[e] = 0.f;

    // ldmatrix lane-address components (verified in pregemm)
    const int a_row  = lid & 15;
    const int a_kof2 = (lid >> 4) * 16;      // byte offset
    const int b_g    = lid >> 3;
    const int b_row  = (b_g >> 1) * 8 + (lid & 7);
    const int b_kof2 = (b_g & 1) * 16;

    for (int t = 0; t < TT; t++) {
        const int tt  = dir ? (TT - 1 - t) : t;
        const int par = t & 1;
        const __nv_bfloat16* hph = &g_hh[LAYER][par][dir][0][0];
        const __nv_bfloat16* hpl = &g_hl[LAYER][par][dir][0][0];

        // ---- load A tile: [x_t(16) |] h_prev(256), hi & lo planes ----
        for (int s = tid; s < 64 * SEGW; s += 256) {
            int r = s / SEGW, seg = s % SEGW;
            int b = m0 + r;
            uint32_t dst = (uint32_t)(r * ROWB + seg * 16);
            if (KIN == 16 && seg < XSEG) {
                size_t xo = ((size_t)b * TT + tt) * IN0 + seg * 8;
                CP_ASYNC16(sA_h + dst, (const char*)(g_x0h + xo));
                CP_ASYNC16(sA_l + dst, (const char*)(g_x0l + xo));
            } else {
                int hs = seg - XSEG;
                CP_ASYNC16(sA_h + dst, (const char*)&hph[b * HH + hs * 8]);
                CP_ASYNC16(sA_l + dst, (const char*)&hpl[b * HH + hs * 8]);
            }
        }
        CP_COMMIT(); CP_WAIT0();
        __syncthreads();

        // ---- MMA: 3-pass split-bf16, K steps of 16 ----
        float c[2][4][4];
#pragma unroll
        for (int mt = 0; mt < 2; mt++)
#pragma unroll
            for (int nt = 0; nt < 4; nt++)
#pragma unroll
                for (int r = 0; r < 4; r++) c[mt][nt][r] = 0.f;

#pragma unroll
        for (int ks = 0; ks < KS; ks++) {
            const int kb = ks * 32;
            uint32_t aH[2][4], aL[2][4], bH[2][4], bL[2][4];
#pragma unroll
            for (int mt = 0; mt < 2; mt++) {
                uint32_t off = (uint32_t)((warp_m * 32 + mt * 16 + a_row) * ROWB + kb + a_kof2);
                LDMATRIX_X4(aH[mt][0], aH[mt][1], aH[mt][2], aH[mt][3], sA_h + off);
                LDMATRIX_X4(aL[mt][0], aL[mt][1], aL[mt][2], aL[mt][3], sA_l + off);
            }
#pragma unroll
            for (int bt = 0; bt < 2; bt++) {
                uint32_t off = (uint32_t)((warp_n * 32 + bt * 16 + b_row) * ROWB + kb + b_kof2);
                LDMATRIX_X4(bH[bt][0], bH[bt][1], bH[bt][2], bH[bt][3], sW_h + off);
                LDMATRIX_X4(bL[bt][0], bL[bt][1], bL[bt][2], bL[bt][3], sW_l + off);
            }
#pragma unroll
            for (int mt = 0; mt < 2; mt++)
#pragma unroll
                for (int nt = 0; nt < 4; nt++) {
                    int bt = nt >> 1, sub = (nt & 1) * 2;
                    MMA_BF16(c[mt][nt][0], c[mt][nt][1], c[mt][nt][2], c[mt][nt][3],
                             aH[mt][0], aH[mt][1], aH[mt][2], aH[mt][3],
                             bH[bt][sub], bH[bt][sub + 1]);
                    MMA_BF16(c[mt][nt][0], c[mt][nt][1], c[mt][nt][2], c[mt][nt][3],
                             aL[mt][0], aL[mt][1], aL[mt][2], aL[mt][3],
                             bH[bt][sub], bH[bt][sub + 1]);
                    MMA_BF16(c[mt][nt][0], c[mt][nt][1], c[mt][nt][2], c[mt][nt][3],
                             aH[mt][0], aH[mt][1], aH[mt][2], aH[mt][3],
                             bL[bt][sub], bL[bt][sub + 1]);
                }
        }
        __syncthreads();   // all ldmatrix reads done before Gs overwrites A planes

        // ---- stage gates to smem: Gs[row][gate*32 + col32] ----
#pragma unroll
        for (int mt = 0; mt < 2; mt++)
#pragma unroll
            for (int nt = 0; nt < 4; nt++) {
                int row = warp_m * 32 + mt * 16 + (lid >> 2);
                int col = warp_n * 32 + nt * 8 + (lid & 3) * 2;
                Gs[row * 132 + col]           = c[mt][nt][0];
                Gs[row * 132 + col + 1]       = c[mt][nt][1];
                Gs[(row + 8) * 132 + col]     = c[mt][nt][2];
                Gs[(row + 8) * 132 + col + 1] = c[mt][nt][3];
            }
        __syncthreads();

        // ---- cell update (c-state in regs), write h as split bf16 ----
        __nv_bfloat16* hnh = &g_hh[LAYER][par ^ 1][dir][0][0];
        __nv_bfloat16* hnl = &g_hl[LAYER][par ^ 1][dir][0][0];
#pragma unroll
        for (int e = 0; e < 8; e++) {
            int p = tid + 256 * e;
            int row = p >> 5, hc = p & 31;
            int b = m0 + row;
            float gi = Gs[row * 132 + hc];
            float gf = Gs[row * 132 + 32 + hc];
            float gg = Gs[row * 132 + 64 + hc];
            float go = Gs[row * 132 + 96 + hc];
            if (LAYER == 0) {
                gi += bias_s[hc];
                gf += bias_s[32 + hc];
                gg += bias_s[64 + hc];
                go += bias_s[96 + hc];
            } else {
                const float* gx = &g_gx1[(((size_t)dir * TT + tt) * BB + b) * NG + n0 + hc];
                gi += gx[0];
                gf += gx[256];
                gg += gx[512];
                go += gx[768];
            }
            float cc = sigf(gf) * cstate[e] + sigf(gi) * tanhf_fast(gg);
            cstate[e] = cc;
            float h = sigf(go) * tanhf_fast(cc);
            __nv_bfloat16 hi = __float2bfloat16(h);
            __nv_bfloat16 lo = __float2bfloat16(h - __bfloat162float(hi));
            size_t ho = (size_t)b * HH + n0 + hc;
            hnh[ho] = hi;
            hnl[ho] = lo;
            if (LAYER == 0) {
                size_t xo = ((size_t)b * TT + tt) * IN1 + dir * HH + n0 + hc;
                g_x1h[xo] = hi;
                g_x1l[xo] = lo;
            }
        }
        group_sync(barr, bgen);
    }
}

// ======================= mma.sync layer-1 input pre-GEMM (unchanged, R7-verified) ======
#define PG_PAD    40
#define PG_HBYTES (128 * PG_PAD * 2)
#define PG_SMEM   (2 * 2 * PG_HBYTES * 2)

__device__ __forceinline__ void pg_load_stage(
    uint32_t sA, uint32_t sW,
    const __nv_bfloat16* Ah, const __nv_bfloat16* Al,
    const __nv_bfloat16* Wh, const __nv_bfloat16* Wl,
    int k0, int tid)
{
#pragma unroll
    for (int i = 0; i < 2; i++) {
        int chunk = tid + 256 * i;
        int row = chunk >> 2, seg = chunk & 3;
        uint32_t doff = (uint32_t)(row * (PG_PAD * 2) + seg * 16);
        const char* a_h = (const char*)(Ah + (size_t)row * IN1 + k0) + seg * 16;
        const char* a_l = (const char*)(Al + (size_t)row * IN1 + k0) + seg * 16;
        const char* w_h = (const char*)(Wh + (size_t)row * IN1 + k0) + seg * 16;
        const char* w_l = (const char*)(Wl + (size_t)row * IN1 + k0) + seg * 16;
        CP_ASYNC16(sA + doff, a_h);
        CP_ASYNC16(sA + PG_HBYTES + doff, a_l);
        CP_ASYNC16(sW + doff, w_h);
        CP_ASYNC16(sW + PG_HBYTES + doff, w_l);
    }
}

__global__ void __launch_bounds__(256, 1) pregemm_mma(
    const float* __restrict__ b1f, const float* __restrict__ b1b)
{
    extern __shared__ char smem[];
    __shared__ float bias_s[128];
    const uint32_t sA0 = smem_u32(smem);
    const uint32_t sW0 = sA0 + 2 * 2 * PG_HBYTES;
    const int tid = threadIdx.x;
    const int wid = tid >> 5, lid = tid & 31;
    const int warp_m = wid >> 2, warp_n = wid & 3;

    const int dir   = blockIdx.x >> 3;
    const int ntile = blockIdx.x & 7;
    const int mtile = blockIdx.y;

    const float* bsrc = dir ? b1b : b1f;
    if (tid < 128) bias_s[tid] = bsrc[ntile * 128 + tid];

    const __nv_bfloat16* Ah = g_x1h + (size_t)mtile * 128 * IN1;
    const __nv_bfloat16* Al = g_x1l + (size_t)mtile * 128 * IN1;
    const __nv_bfloat16* Wh = &g_w1h[dir][ntile * 128][0];
    const __nv_bfloat16* Wl = &g_w1l[dir][ntile * 128][0];

    float c[4][4][4];
#pragma unroll
    for (int mt = 0; mt < 4; mt++)
#pragma unroll
        for (int nt = 0; nt < 4; nt++)
#pragma unroll
            for (int r = 0; r < 4; r++) c[mt][nt][r] = 0.f;

    pg_load_stage(sA0, sW0, Ah, Al, Wh, Wl, 0, tid);  CP_COMMIT();
    pg_load_stage(sA0 + 2 * PG_HBYTES, sW0 + 2 * PG_HBYTES, Ah, Al, Wh, Wl, 32, tid); CP_COMMIT();

    const int a_row = (lid & 15);
    const int a_kof = (lid >> 4) * 8;
    const int b_g   = lid >> 3;
    const int b_row = (b_g >> 1) * 8 + (lid & 7);
    const int b_kof = (b_g & 1) * 8;

    for (int ci = 0; ci < 16; ci++) {
        const int st = ci & 1;
        if (ci == 15) CP_WAIT0(); else CP_WAIT1();
        __syncthreads();

        const uint32_t sA = sA0 + st * 2 * PG_HBYTES;
        const uint32_t sW = sW0 + st * 2 * PG_HBYTES;

#pragma unroll
        for (int ks = 0; ks < 32; ks += 16) {
            uint32_t aH[4][4], aL[4][4], bH[2][4], bL[2][4];
#pragma unroll
            for (int mt = 0; mt < 4; mt++) {
                int row = warp_m * 64 + mt * 16 + a_row;
                uint32_t off = (uint32_t)(row * (PG_PAD * 2) + (ks + a_kof) * 2);
                LDMATRIX_X4(aH[mt][0], aH[mt][1], aH[mt][2], aH[mt][3], sA + off);
                LDMATRIX_X4(aL[mt][0], aL[mt][1], aL[mt][2], aL[mt][3], sA + PG_HBYTES + off);
            }
#pragma unroll
            for (int bt = 0; bt < 2; bt++) {
                int row = warp_n * 32 + bt * 16 + b_row;
                uint32_t off = (uint32_t)(row * (PG_PAD * 2) + (ks + b_kof) * 2);
                LDMATRIX_X4(bH[bt][0], bH[bt][1], bH[bt][2], bH[bt][3], sW + off);
                LDMATRIX_X4(bL[bt][0], bL[bt][1], bL[bt][2], bL[bt][3], sW + PG_HBYTES + off);
            }
#pragma unroll
            for (int mt = 0; mt < 4; mt++)
#pragma unroll
                for (int nt = 0; nt < 4; nt++) {
                    int bt = nt >> 1, sub = (nt & 1) * 2;
                    MMA_BF16(c[mt][nt][0], c[mt][nt][1], c[mt][nt][2], c[mt][nt][3],
                             aH[mt][0], aH[mt][1], aH[mt][2], aH[mt][3],
                             bH[bt][sub], bH[bt][sub + 1]);
                    MMA_BF16(c[mt][nt][0], c[mt][nt][1], c[mt][nt][2], c[mt][nt][3],
                             aL[mt][0], aL[mt][1], aL[mt][2], aL[mt][3],
                             bH[bt][sub], bH[bt][sub + 1]);
                    MMA_BF16(c[mt][nt][0], c[mt][nt][1], c[mt][nt][2], c[mt][nt][3],
                             aH[mt][0], aH[mt][1], aH[mt][2], aH[mt][3],
                             bL[bt][sub], bL[bt][sub + 1]);
                }
        }
        __syncthreads();
        if (ci + 2 < 16) {
            pg_load_stage(sA, sW, Ah, Al, Wh, Wl, (ci + 2) * 32, tid);
            CP_COMMIT();
        }
    }

#pragma unroll
    for (int mt = 0; mt < 4; mt++) {
#pragma unroll
        for (int rh = 0; rh < 2; rh++) {
            int row = warp_m * 64 + mt * 16 + (lid >> 2) + rh * 8;
            size_t R = (size_t)mtile * 128 + row;
            int b = (int)(R >> 9), t = (int)(R & 511);
            float* dst = g_gx1 + (((size_t)dir * TT + t) * BB + b) * NG + ntile * 128;
#pragma unroll
            for (int nt = 0; nt < 4; nt++) {
                int col = warp_n * 32 + nt * 8 + (lid & 3) * 2;
                float2 v;
                v.x = c[mt][nt][rh * 2 + 0] + bias_s[col];
                v.y = c[mt][nt][rh * 2 + 1] + bias_s[col + 1];
                *(float2*)(dst + col) = v;
            }
        }
    }
}

// ======================= final projection =======================
__global__ void fc_kernel(const float* __restrict__ fcw, const float* __restrict__ fcb,
                          float* __restrict__ out)
{
    int b = blockIdx.x;
    int l = threadIdx.x;   // 64 threads
    __shared__ float hs[2 * HH];
    for (int j = threadIdx.x; j < 2 * HH; j += blockDim.x) {
        int d = j >> 8, jj = j & 255;
        hs[j] = __bfloat162float(g_hh[1][0][d][b][jj]) + __bfloat162float(g_hl[1][0][d][b][jj]);
    }
    __syncthreads();
    float s = fcb[l];
#pragma unroll 8
    for (int j = 0; j < 2 * HH; j++)
        s = fmaf(hs[j], fcw[l * (2 * HH) + j], s);
    out[b * LOUT + l] = s;
}

// ---------------- launch ----------------
extern "C" void kernel_launch(void* const* d_in, const int* in_sizes, int n_in,
                              void* d_out, int out_size)
{
    const float* x     = (const float*)d_in[0];
    const float* wih0f = (const float*)d_in[1];
    const float* whh0f = (const float*)d_in[2];
    const float* b0f   = (const float*)d_in[3];
    const float* wih0b = (const float*)d_in[4];
    const float* whh0b = (const float*)d_in[5];
    const float* b0b   = (const float*)d_in[6];
    const float* wih1f = (const float*)d_in[7];
    const float* whh1f = (const float*)d_in[8];
    const float* b1f   = (const float*)d_in[9];
    const float* wih1b = (const float*)d_in[10];
    const float* whh1b = (const float*)d_in[11];
    const float* b1b   = (const float*)d_in[12];
    const float* fcw   = (const float*)d_in[13];
    const float* fcb   = (const float*)d_in[14];
    float* out = (float*)d_out;

    const int SM0 = 384 * ((IN0 + HH + 8) * 2);   // 215040
    const int SM1 = 384 * ((HH + 8) * 2);         // 202752
    cudaFuncSetAttribute(lstm_seq_tc<16>, cudaFuncAttributeMaxDynamicSharedMemorySize, SM0);
    cudaFuncSetAttribute(lstm_seq_tc<0>,  cudaFuncAttributeMaxDynamicSharedMemorySize, SM1);
    cudaFuncSetAttribute(pregemm_mma, cudaFuncAttributeMaxDynamicSharedMemorySize, PG_SMEM);

    __nv_bfloat16 *p_x0h, *p_x0l, *p_w0h0, *p_w0l0, *p_w0h1, *p_w0l1;
    __nv_bfloat16 *p_wh[2][2], *p_wl[2][2];
    cudaGetSymbolAddress((void**)&p_x0h, g_x0h);
    cudaGetSymbolAddress((void**)&p_x0l, g_x0l);
    // symbol base pointers via address-of-first-element trick through kernels is
    // not possible host-side; instead use cudaGetSymbolAddress on the arrays:
    void *a_w0h, *a_w0l, *a_whh_h, *a_whh_l;
    cudaGetSymbolAddress(&a_w0h, g_w0h);
    cudaGetSymbolAddress(&a_w0l, g_w0l);
    cudaGetSymbolAddress(&a_whh_h, g_whh_h);
    cudaGetSymbolAddress(&a_whh_l, g_whh_l);
    p_w0h0 = (__nv_bfloat16*)a_w0h;
    p_w0l0 = (__nv_bfloat16*)a_w0l;
    p_w0h1 = p_w0h0 + NG * IN0;
    p_w0l1 = p_w0l0 + NG * IN0;
    for (int L = 0; L < 2; L++)
        for (int d = 0; d < 2; d++) {
            p_wh[L][d] = (__nv_bfloat16*)a_whh_h + ((size_t)L * 2 + d) * NG * HH;
            p_wl[L][d] = (__nv_bfloat16*)a_whh_l + ((size_t)L * 2 + d) * NG * HH;
        }

    zero_kernel<<<128, 256>>>();
    split_kernel<<<512, 256>>>(x, p_x0h, p_x0l, BB * TT * IN0);
    split_kernel<<<64, 256>>>(wih0f, p_w0h0, p_w0l0, NG * IN0);
    split_kernel<<<64, 256>>>(wih0b, p_w0h1, p_w0l1, NG * IN0);
    split_kernel<<<256, 256>>>(whh0f, p_wh[0][0], p_wl[0][0], NG * HH);
    split_kernel<<<256, 256>>>(whh0b, p_wh[0][1], p_wl[0][1], NG * HH);
    split_kernel<<<256, 256>>>(whh1f, p_wh[1][0], p_wl[1][0], NG * HH);
    split_kernel<<<256, 256>>>(whh1b, p_wh[1][1], p_wl[1][1], NG * HH);
    conv_w1_kernel<<<512, 256>>>(wih1f, wih1b);

    lstm_seq_tc<16><<<128, 256, SM0>>>(b0f, b0b);

    dim3 gt(16, 2048, 1);
    pregemm_mma<<<gt, 256, PG_SMEM>>>(b1f, b1b);

    lstm_seq_tc<0><<<128, 256, SM1>>>(nullptr, nullptr);

    fc_kernel<<<BB, LOUT>>>(fcw, fcb, out);
}

// round 9
// speedup vs baseline: 2.5354x; 1.0099x over previous
#include <cuda_runtime.h>
#include <cuda_bf16.h>
#include <cstdint>
#include <math.h>

// Problem dims
#define BB   512
#define TT   512
#define IN0  16
#define HH   256
#define NG   1024          // 4*H
#define IN1  (2 * HH)      // 512
#define LOUT 64

// ---------------- device scratch (static, no allocations) ----------------
__device__ float g_gx1 [(size_t)2 * TT * BB * NG];     // layer-1 input-GEMM precompute (+bias)
__device__ __nv_bfloat16 g_x1h[(size_t)BB * TT * IN1]; // split-bf16 hi of x1 (layer-0 output)
__device__ __nv_bfloat16 g_x1l[(size_t)BB * TT * IN1];
__device__ __nv_bfloat16 g_w1h[2][NG][IN1];            // split-bf16 of w_ih1
__device__ __nv_bfloat16 g_w1l[2][NG][IN1];
__device__ __nv_bfloat16 g_x0h[(size_t)BB * TT * IN0]; // split-bf16 of x
__device__ __nv_bfloat16 g_x0l[(size_t)BB * TT * IN0];
__device__ __nv_bfloat16 g_w0h[2][NG][IN0];            // split-bf16 of w_ih0
__device__ __nv_bfloat16 g_w0l[2][NG][IN0];
__device__ __nv_bfloat16 g_whh_h[2][2][NG][HH];        // [layer][dir]
__device__ __nv_bfloat16 g_whh_l[2][2][NG][HH];
__device__ __nv_bfloat16 g_hh[2][2][2][BB][HH];        // [layer][parity][dir][b][j]
__device__ __nv_bfloat16 g_hl[2][2][2][BB][HH];
__device__ unsigned g_garr[2][16];
__device__ unsigned g_ggen[2][16];

__global__ void zero_kernel()
{
    int tid = blockIdx.x * blockDim.x + threadIdx.x;
    int stride = gridDim.x * blockDim.x;
    const int nh = 2 * 2 * 2 * BB * HH / 2;   // uint count per array
    for (int i = tid; i < nh; i += stride) {
        ((unsigned*)g_hh)[i] = 0u;
        ((unsigned*)g_hl)[i] = 0u;
    }
    if (tid < 32) {
        ((unsigned*)g_garr)[tid] = 0u;
        ((unsigned*)g_ggen)[tid] = 0u;
    }
}

__device__ __forceinline__ float sigf(float x) { return 1.f / (1.f + __expf(-x)); }
__device__ __forceinline__ float tanhf_fast(float x) { return 2.f / (1.f + __expf(-2.f * x)) - 1.f; }

// ======================= helpers =======================
__device__ __forceinline__ uint32_t smem_u32(const void* p) {
    uint32_t a;
    asm("{ .reg .u64 t; cvta.to.shared.u64 t, %1; cvt.u32.u64 %0, t; }" : "=r"(a) : "l"(p));
    return a;
}
#define CP_ASYNC16(dst, src) \
    asm volatile("cp.async.cg.shared.global [%0], [%1], 16;" :: "r"(dst), "l"(src) : "memory")
#define CP_COMMIT() asm volatile("cp.async.commit_group;" ::: "memory")
#define CP_WAIT2()  asm volatile("cp.async.wait_group 2;" ::: "memory")
#define CP_WAIT0()  asm volatile("cp.async.wait_group 0;" ::: "memory")
#define LDMATRIX_X4(r0, r1, r2, r3, addr) \
    asm volatile("ldmatrix.sync.aligned.m8n8.x4.shared.b16 {%0,%1,%2,%3}, [%4];" \
                 : "=r"(r0), "=r"(r1), "=r"(r2), "=r"(r3) : "r"(addr))
#define MMA_BF16(c0, c1, c2, c3, a0, a1, a2, a3, b0, b1) \
    asm volatile("mma.sync.aligned.m16n8k16.row.col.f32.bf16.bf16.f32 " \
                 "{%0,%1,%2,%3}, {%4,%5,%6,%7}, {%8,%9}, {%0,%1,%2,%3};" \
                 : "+f"(c0), "+f"(c1), "+f"(c2), "+f"(c3) \
                 : "r"(a0), "r"(a1), "r"(a2), "r"(a3), "r"(b0), "r"(b1))

// ---------------- per-group (8-block) barrier ----------------
__device__ __forceinline__ void group_sync(unsigned* arr, unsigned* gen)
{
    __syncthreads();
    if (threadIdx.x == 0) {
        __threadfence();
        unsigned g = *(volatile unsigned*)gen;
        if (atomicAdd(arr, 1u) == 7u) {
            atomicExch(arr, 0u);
            __threadfence();
            atomicAdd(gen, 1u);
        } else {
            while (*(volatile unsigned*)gen == g) { __nanosleep(32); }
        }
        __threadfence();
    }
    __syncthreads();
}

// ======================= split-bf16 conversion =======================
__global__ void split_kernel(const float* __restrict__ src,
                             __nv_bfloat16* __restrict__ dh,
                             __nv_bfloat16* __restrict__ dl, int n)
{
    int i = blockIdx.x * blockDim.x + threadIdx.x;
    int stride = gridDim.x * blockDim.x;
    for (; i < n; i += stride) {
        float v = src[i];
        __nv_bfloat16 h = __float2bfloat16(v);
        dh[i] = h;
        dl[i] = __float2bfloat16(v - __bfloat162float(h));
    }
}

__global__ void conv_w1_kernel(const float* __restrict__ wf, const float* __restrict__ wb)
{
    const int n = NG * IN1;
    int i = blockIdx.x * blockDim.x + threadIdx.x;
    int stride = gridDim.x * blockDim.x;
    for (; i < 2 * n; i += stride) {
        int d = i / n, r = i % n;
        float v = (d ? wb : wf)[r];
        __nv_bfloat16 h = __float2bfloat16(v);
        ((__nv_bfloat16*)g_w1h)[i] = h;
        ((__nv_bfloat16*)g_w1l)[i] = __float2bfloat16(v - __bfloat162float(h));
    }
}

// ======================= tensorized persistent LSTM layer (R8-verified) ===========
template<int KIN>
__global__ void __launch_bounds__(256, 1) lstm_seq_tc(
    const float* __restrict__ bias_f, const float* __restrict__ bias_b)
{
    constexpr int LAYER = (KIN == 16) ? 0 : 1;
    constexpr int K     = KIN + HH;          // 272 / 256
    constexpr int KS    = K / 16;            // 17 / 16
    constexpr int SEGW  = K / 8;             // 34 / 32
    constexpr int XSEG  = KIN / 8;           // 2 / 0
    constexpr int ROWB  = (K + 8) * 2;       // 560 / 528

    extern __shared__ char smem[];
    const uint32_t sA_h = smem_u32(smem);
    const uint32_t sA_l = sA_h + 64 * ROWB;
    const uint32_t sW_h = sA_l + 64 * ROWB;
    const uint32_t sW_l = sW_h + 128 * ROWB;
    float* Gs = (float*)smem;                // aliases A planes
    __shared__ float bias_s[128];

    const int tid = threadIdx.x;
    const int wid = tid >> 5, lid = tid & 31;
    const int warp_m = wid >> 2, warp_n = wid & 3;
    const int bx = blockIdx.x;
    const int n_idx = bx & 7, m_idx = (bx >> 3) & 7, dir = bx >> 6;
    const int n0 = n_idx * 32, m0 = m_idx * 64;
    unsigned* barr = &g_garr[LAYER][dir * 8 + m_idx];
    unsigned* bgen = &g_ggen[LAYER][dir * 8 + m_idx];

    if (LAYER == 0 && tid < 128)
        bias_s[tid] = (dir ? bias_b : bias_f)[(tid >> 5) * 256 + n0 + (tid & 31)];

    {
        const __nv_bfloat16* wh = &g_whh_h[LAYER][dir][0][0];
        const __nv_bfloat16* wl = &g_whh_l[LAYER][dir][0][0];
        for (int s = tid; s < 128 * SEGW; s += 256) {
            int r = s / SEGW, seg = s % SEGW;
            int n = (r >> 5) * 256 + n0 + (r & 31);
            uint32_t dst = (uint32_t)(r * ROWB + seg * 16);
            if (KIN == 16 && seg < XSEG) {
                CP_ASYNC16(sW_h + dst, (const char*)&g_w0h[dir][n][seg * 8]);
                CP_ASYNC16(sW_l + dst, (const char*)&g_w0l[dir][n][seg * 8]);
            } else {
                int hs = seg - XSEG;
                CP_ASYNC16(sW_h + dst, (const char*)&wh[n * HH + hs * 8]);
                CP_ASYNC16(sW_l + dst, (const char*)&wl[n * HH + hs * 8]);
            }
        }
        CP_COMMIT(); CP_WAIT0();
        __syncthreads();
    }

    float cstate[8];
#pragma unroll
    for (int e = 0; e < 8; e++) cstate[e] = 0.f;

    const int a_row  = lid & 15;
    const int a_kof2 = (lid >> 4) * 16;
    const int b_g    = lid >> 3;
    const int b_row  = (b_g >> 1) * 8 + (lid & 7);
    const int b_kof2 = (b_g & 1) * 16;

    for (int t = 0; t < TT; t++) {
        const int tt  = dir ? (TT - 1 - t) : t;
        const int par = t & 1;
        const __nv_bfloat16* hph = &g_hh[LAYER][par][dir][0][0];
        const __nv_bfloat16* hpl = &g_hl[LAYER][par][dir][0][0];

        for (int s = tid; s < 64 * SEGW; s += 256) {
            int r = s / SEGW, seg = s % SEGW;
            int b = m0 + r;
            uint32_t dst = (uint32_t)(r * ROWB + seg * 16);
            if (KIN == 16 && seg < XSEG) {
                size_t xo = ((size_t)b * TT + tt) * IN0 + seg * 8;
                CP_ASYNC16(sA_h + dst, (const char*)(g_x0h + xo));
                CP_ASYNC16(sA_l + dst, (const char*)(g_x0l + xo));
            } else {
                int hs = seg - XSEG;
                CP_ASYNC16(sA_h + dst, (const char*)&hph[b * HH + hs * 8]);
                CP_ASYNC16(sA_l + dst, (const char*)&hpl[b * HH + hs * 8]);
            }
        }
        CP_COMMIT(); CP_WAIT0();
        __syncthreads();

        float c[2][4][4];
#pragma unroll
        for (int mt = 0; mt < 2; mt++)
#pragma unroll
            for (int nt = 0; nt < 4; nt++)
#pragma unroll
                for (int r = 0; r < 4; r++) c[mt][nt][r] = 0.f;

#pragma unroll
        for (int ks = 0; ks < KS; ks++) {
            const int kb = ks * 32;
            uint32_t aH[2][4], aL[2][4], bH[2][4], bL[2][4];
#pragma unroll
            for (int mt = 0; mt < 2; mt++) {
                uint32_t off = (uint32_t)((warp_m * 32 + mt * 16 + a_row) * ROWB + kb + a_kof2);
                LDMATRIX_X4(aH[mt][0], aH[mt][1], aH[mt][2], aH[mt][3], sA_h + off);
                LDMATRIX_X4(aL[mt][0], aL[mt][1], aL[mt][2], aL[mt][3], sA_l + off);
            }
#pragma unroll
            for (int bt = 0; bt < 2; bt++) {
                uint32_t off = (uint32_t)((warp_n * 32 + bt * 16 + b_row) * ROWB + kb + b_kof2);
                LDMATRIX_X4(bH[bt][0], bH[bt][1], bH[bt][2], bH[bt][3], sW_h + off);
                LDMATRIX_X4(bL[bt][0], bL[bt][1], bL[bt][2], bL[bt][3], sW_l + off);
            }
#pragma unroll
            for (int mt = 0; mt < 2; mt++)
#pragma unroll
                for (int nt = 0; nt < 4; nt++) {
                    int bt = nt >> 1, sub = (nt & 1) * 2;
                    MMA_BF16(c[mt][nt][0], c[mt][nt][1], c[mt][nt][2], c[mt][nt][3],
                             aH[mt][0], aH[mt][1], aH[mt][2], aH[mt][3],
                             bH[bt][sub], bH[bt][sub + 1]);
                    MMA_BF16(c[mt][nt][0], c[mt][nt][1], c[mt][nt][2], c[mt][nt][3],
                             aL[mt][0], aL[mt][1], aL[mt][2], aL[mt][3],
                             bH[bt][sub], bH[bt][sub + 1]);
                    MMA_BF16(c[mt][nt][0], c[mt][nt][1], c[mt][nt][2], c[mt][nt][3],
                             aH[mt][0], aH[mt][1], aH[mt][2], aH[mt][3],
                             bL[bt][sub], bL[bt][sub + 1]);
                }
        }
        __syncthreads();

#pragma unroll
        for (int mt = 0; mt < 2; mt++)
#pragma unroll
            for (int nt = 0; nt < 4; nt++) {
                int row = warp_m * 32 + mt * 16 + (lid >> 2);
                int col = warp_n * 32 + nt * 8 + (lid & 3) * 2;
                Gs[row * 132 + col]           = c[mt][nt][0];
                Gs[row * 132 + col + 1]       = c[mt][nt][1];
                Gs[(row + 8) * 132 + col]     = c[mt][nt][2];
                Gs[(row + 8) * 132 + col + 1] = c[mt][nt][3];
            }
        __syncthreads();

        __nv_bfloat16* hnh = &g_hh[LAYER][par ^ 1][dir][0][0];
        __nv_bfloat16* hnl = &g_hl[LAYER][par ^ 1][dir][0][0];
#pragma unroll
        for (int e = 0; e < 8; e++) {
            int p = tid + 256 * e;
            int row = p >> 5, hc = p & 31;
            int b = m0 + row;
            float gi = Gs[row * 132 + hc];
            float gf = Gs[row * 132 + 32 + hc];
            float gg = Gs[row * 132 + 64 + hc];
            float go = Gs[row * 132 + 96 + hc];
            if (LAYER == 0) {
                gi += bias_s[hc];
                gf += bias_s[32 + hc];
                gg += bias_s[64 + hc];
                go += bias_s[96 + hc];
            } else {
                const float* gx = &g_gx1[(((size_t)dir * TT + tt) * BB + b) * NG + n0 + hc];
                gi += gx[0];
                gf += gx[256];
                gg += gx[512];
                go += gx[768];
            }
            float cc = sigf(gf) * cstate[e] + sigf(gi) * tanhf_fast(gg);
            cstate[e] = cc;
            float h = sigf(go) * tanhf_fast(cc);
            __nv_bfloat16 hi = __float2bfloat16(h);
            __nv_bfloat16 lo = __float2bfloat16(h - __bfloat162float(hi));
            size_t ho = (size_t)b * HH + n0 + hc;
            hnh[ho] = hi;
            hnl[ho] = lo;
            if (LAYER == 0) {
                size_t xo = ((size_t)b * TT + tt) * IN1 + dir * HH + n0 + hc;
                g_x1h[xo] = hi;
                g_x1l[xo] = lo;
            }
        }
        group_sync(barr, bgen);
    }
}

// ======================= layer-1 input pre-GEMM: 4-stage pipeline ======
#define PG_PAD    40
#define PG_HBYTES (128 * PG_PAD * 2)               // 10240 per plane
#define PG_STAGE  (4 * PG_HBYTES)                  // 40960 per stage (Ah,Al,Wh,Wl)
#define PG_NSTG   4
#define PG_SMEM   (PG_NSTG * PG_STAGE)             // 163840

__device__ __forceinline__ void pg_load_stage(
    uint32_t sbase,
    const __nv_bfloat16* Ah, const __nv_bfloat16* Al,
    const __nv_bfloat16* Wh, const __nv_bfloat16* Wl,
    int k0, int tid)
{
#pragma unroll
    for (int i = 0; i < 2; i++) {
        int chunk = tid + 256 * i;          // 512 chunks: 128 rows x 4 segs
        int row = chunk >> 2, seg = chunk & 3;
        uint32_t doff = (uint32_t)(row * (PG_PAD * 2) + seg * 16);
        const char* a_h = (const char*)(Ah + (size_t)row * IN1 + k0) + seg * 16;
        const char* a_l = (const char*)(Al + (size_t)row * IN1 + k0) + seg * 16;
        const char* w_h = (const char*)(Wh + (size_t)row * IN1 + k0) + seg * 16;
        const char* w_l = (const char*)(Wl + (size_t)row * IN1 + k0) + seg * 16;
        CP_ASYNC16(sbase + doff, a_h);
        CP_ASYNC16(sbase + PG_HBYTES + doff, a_l);
        CP_ASYNC16(sbase + 2 * PG_HBYTES + doff, w_h);
        CP_ASYNC16(sbase + 3 * PG_HBYTES + doff, w_l);
    }
}

__global__ void __launch_bounds__(256, 1) pregemm_mma(
    const float* __restrict__ b1f, const float* __restrict__ b1b)
{
    extern __shared__ char smem[];
    __shared__ float bias_s[128];
    const uint32_t s0 = smem_u32(smem);
    const int tid = threadIdx.x;
    const int wid = tid >> 5, lid = tid & 31;
    const int warp_m = wid >> 2, warp_n = wid & 3;

    const int dir   = blockIdx.x >> 3;
    const int ntile = blockIdx.x & 7;
    const int mtile = blockIdx.y;

    const float* bsrc = dir ? b1b : b1f;
    if (tid < 128) bias_s[tid] = bsrc[ntile * 128 + tid];

    const __nv_bfloat16* Ah = g_x1h + (size_t)mtile * 128 * IN1;
    const __nv_bfloat16* Al = g_x1l + (size_t)mtile * 128 * IN1;
    const __nv_bfloat16* Wh = &g_w1h[dir][ntile * 128][0];
    const __nv_bfloat16* Wl = &g_w1l[dir][ntile * 128][0];

    float c[4][4][4];
#pragma unroll
    for (int mt = 0; mt < 4; mt++)
#pragma unroll
        for (int nt = 0; nt < 4; nt++)
#pragma unroll
            for (int r = 0; r < 4; r++) c[mt][nt][r] = 0.f;

    // prologue: stages 0,1,2
    pg_load_stage(s0 + 0 * PG_STAGE, Ah, Al, Wh, Wl, 0,  tid); CP_COMMIT();
    pg_load_stage(s0 + 1 * PG_STAGE, Ah, Al, Wh, Wl, 32, tid); CP_COMMIT();
    pg_load_stage(s0 + 2 * PG_STAGE, Ah, Al, Wh, Wl, 64, tid); CP_COMMIT();

    const int a_row = (lid & 15);
    const int a_kof = (lid >> 4) * 8;
    const int b_g   = lid >> 3;
    const int b_row = (b_g >> 1) * 8 + (lid & 7);
    const int b_kof = (b_g & 1) * 8;

    for (int ci = 0; ci < 16; ci++) {
        if (ci >= 13) CP_WAIT0(); else CP_WAIT2();  // stage ci complete
        __syncthreads();                            // all warps done with stage ci-1's buffer

        // issue the load for stage ci+3 into buffer (ci+3)&3 (consumed at ci-1)
        if (ci + 3 < 16) {
            pg_load_stage(s0 + ((ci + 3) & 3) * PG_STAGE, Ah, Al, Wh, Wl, (ci + 3) * 32, tid);
            CP_COMMIT();
        }

        const uint32_t sb = s0 + (ci & 3) * PG_STAGE;
        const uint32_t sA = sb;
        const uint32_t sW = sb + 2 * PG_HBYTES;

#pragma unroll
        for (int ks = 0; ks < 32; ks += 16) {
            uint32_t aH[4][4], aL[4][4], bH[2][4], bL[2][4];
#pragma unroll
            for (int mt = 0; mt < 4; mt++) {
                int row = warp_m * 64 + mt * 16 + a_row;
                uint32_t off = (uint32_t)(row * (PG_PAD * 2) + (ks + a_kof) * 2);
                LDMATRIX_X4(aH[mt][0], aH[mt][1], aH[mt][2], aH[mt][3], sA + off);
                LDMATRIX_X4(aL[mt][0], aL[mt][1], aL[mt][2], aL[mt][3], sA + PG_HBYTES + off);
            }
#pragma unroll
            for (int bt = 0; bt < 2; bt++) {
                int row = warp_n * 32 + bt * 16 + b_row;
                uint32_t off = (uint32_t)(row * (PG_PAD * 2) + (ks + b_kof) * 2);
                LDMATRIX_X4(bH[bt][0], bH[bt][1], bH[bt][2], bH[bt][3], sW + off);
                LDMATRIX_X4(bL[bt][0], bL[bt][1], bL[bt][2], bL[bt][3], sW + PG_HBYTES + off);
            }
#pragma unroll
            for (int mt = 0; mt < 4; mt++)
#pragma unroll
                for (int nt = 0; nt < 4; nt++) {
                    int bt = nt >> 1, sub = (nt & 1) * 2;
                    MMA_BF16(c[mt][nt][0], c[mt][nt][1], c[mt][nt][2], c[mt][nt][3],
                             aH[mt][0], aH[mt][1], aH[mt][2], aH[mt][3],
                             bH[bt][sub], bH[bt][sub + 1]);
                    MMA_BF16(c[mt][nt][0], c[mt][nt][1], c[mt][nt][2], c[mt][nt][3],
                             aL[mt][0], aL[mt][1], aL[mt][2], aL[mt][3],
                             bH[bt][sub], bH[bt][sub + 1]);
                    MMA_BF16(c[mt][nt][0], c[mt][nt][1], c[mt][nt][2], c[mt][nt][3],
                             aH[mt][0], aH[mt][1], aH[mt][2], aH[mt][3],
                             bL[bt][sub], bL[bt][sub + 1]);
                }
        }
    }

#pragma unroll
    for (int mt = 0; mt < 4; mt++) {
#pragma unroll
        for (int rh = 0; rh < 2; rh++) {
            int row = warp_m * 64 + mt * 16 + (lid >> 2) + rh * 8;
            size_t R = (size_t)mtile * 128 + row;
            int b = (int)(R >> 9), t = (int)(R & 511);
            float* dst = g_gx1 + (((size_t)dir * TT + t) * BB + b) * NG + ntile * 128;
#pragma unroll
            for (int nt = 0; nt < 4; nt++) {
                int col = warp_n * 32 + nt * 8 + (lid & 3) * 2;
                float2 v;
                v.x = c[mt][nt][rh * 2 + 0] + bias_s[col];
                v.y = c[mt][nt][rh * 2 + 1] + bias_s[col + 1];
                *(float2*)(dst + col) = v;
            }
        }
    }
}

// ======================= final projection =======================
__global__ void fc_kernel(const float* __restrict__ fcw, const float* __restrict__ fcb,
                          float* __restrict__ out)
{
    int b = blockIdx.x;
    int l = threadIdx.x;   // 64 threads
    __shared__ float hs[2 * HH];
    for (int j = threadIdx.x; j < 2 * HH; j += blockDim.x) {
        int d = j >> 8, jj = j & 255;
        hs[j] = __bfloat162float(g_hh[1][0][d][b][jj]) + __bfloat162float(g_hl[1][0][d][b][jj]);
    }
    __syncthreads();
    float s = fcb[l];
#pragma unroll 8
    for (int j = 0; j < 2 * HH; j++)
        s = fmaf(hs[j], fcw[l * (2 * HH) + j], s);
    out[b * LOUT + l] = s;
}

// ---------------- launch ----------------
extern "C" void kernel_launch(void* const* d_in, const int* in_sizes, int n_in,
                              void* d_out, int out_size)
{
    const float* x     = (const float*)d_in[0];
    const float* wih0f = (const float*)d_in[1];
    const float* whh0f = (const float*)d_in[2];
    const float* b0f   = (const float*)d_in[3];
    const float* wih0b = (const float*)d_in[4];
    const float* whh0b = (const float*)d_in[5];
    const float* b0b   = (const float*)d_in[6];
    const float* wih1f = (const float*)d_in[7];
    const float* whh1f = (const float*)d_in[8];
    const float* b1f   = (const float*)d_in[9];
    const float* wih1b = (const float*)d_in[10];
    const float* whh1b = (const float*)d_in[11];
    const float* b1b   = (const float*)d_in[12];
    const float* fcw   = (const float*)d_in[13];
    const float* fcb   = (const float*)d_in[14];
    float* out = (float*)d_out;

    const int SM0 = 384 * ((IN0 + HH + 8) * 2);   // 215040
    const int SM1 = 384 * ((HH + 8) * 2);         // 202752
    cudaFuncSetAttribute(lstm_seq_tc<16>, cudaFuncAttributeMaxDynamicSharedMemorySize, SM0);
    cudaFuncSetAttribute(lstm_seq_tc<0>,  cudaFuncAttributeMaxDynamicSharedMemorySize, SM1);
    cudaFuncSetAttribute(pregemm_mma, cudaFuncAttributeMaxDynamicSharedMemorySize, PG_SMEM);

    void *a_x0h, *a_x0l, *a_w0h, *a_w0l, *a_whh_h, *a_whh_l;
    cudaGetSymbolAddress(&a_x0h, g_x0h);
    cudaGetSymbolAddress(&a_x0l, g_x0l);
    cudaGetSymbolAddress(&a_w0h, g_w0h);
    cudaGetSymbolAddress(&a_w0l, g_w0l);
    cudaGetSymbolAddress(&a_whh_h, g_whh_h);
    cudaGetSymbolAddress(&a_whh_l, g_whh_l);
    __nv_bfloat16* p_x0h = (__nv_bfloat16*)a_x0h;
    __nv_bfloat16* p_x0l = (__nv_bfloat16*)a_x0l;
    __nv_bfloat16* p_w0h0 = (__nv_bfloat16*)a_w0h;
    __nv_bfloat16* p_w0l0 = (__nv_bfloat16*)a_w0l;
    __nv_bfloat16* p_w0h1 = p_w0h0 + NG * IN0;
    __nv_bfloat16* p_w0l1 = p_w0l0 + NG * IN0;
    __nv_bfloat16 *p_wh[2][2], *p_wl[2][2];
    for (int L = 0; L < 2; L++)
        for (int d = 0; d < 2; d++) {
            p_wh[L][d] = (__nv_bfloat16*)a_whh_h + ((size_t)L * 2 + d) * NG * HH;
            p_wl[L][d] = (__nv_bfloat16*)a_whh_l + ((size_t)L * 2 + d) * NG * HH;
        }

    zero_kernel<<<128, 256>>>();
    split_kernel<<<512, 256>>>(x, p_x0h, p_x0l, BB * TT * IN0);
    split_kernel<<<64, 256>>>(wih0f, p_w0h0, p_w0l0, NG * IN0);
    split_kernel<<<64, 256>>>(wih0b, p_w0h1, p_w0l1, NG * IN0);
    split_kernel<<<256, 256>>>(whh0f, p_wh[0][0], p_wl[0][0], NG * HH);
    split_kernel<<<256, 256>>>(whh0b, p_wh[0][1], p_wl[0][1], NG * HH);
    split_kernel<<<256, 256>>>(whh1f, p_wh[1][0], p_wl[1][0], NG * HH);
    split_kernel<<<256, 256>>>(whh1b, p_wh[1][1], p_wl[1][1], NG * HH);
    conv_w1_kernel<<<512, 256>>>(wih1f, wih1b);

    lstm_seq_tc<16><<<128, 256, SM0>>>(b0f, b0b);

    dim3 gt(16, 2048, 1);
    pregemm_mma<<<gt, 256, PG_SMEM>>>(b1f, b1b);

    lstm_seq_tc<0><<<128, 256, SM1>>>(nullptr, nullptr);

    fc_kernel<<<BB, LOUT>>>(fcw, fcb, out);
}

// round 10
// speedup vs baseline: 3.0951x; 1.2208x over previous
#include <cuda_runtime.h>
#include <cuda_fp16.h>
#include <cstdint>
#include <math.h>

// Problem dims
#define BB   512
#define TT   512
#define IN0  16
#define HH   256
#define NG   1024          // 4*H
#define IN1  (2 * HH)      // 512
#define LOUT 64

// ---------------- device scratch (static, no allocations) ----------------
__device__ float g_gx1 [(size_t)2 * TT * BB * NG];   // layer-1 input-GEMM precompute (+bias)
__device__ __half g_x1h[(size_t)BB * TT * IN1];      // split-fp16 hi of x1 (layer-0 output)
__device__ __half g_x1l[(size_t)BB * TT * IN1];
__device__ __half g_w1 [2][NG][IN1];                 // fp16 w_ih1
__device__ __half g_x0h[(size_t)BB * TT * IN0];      // split-fp16 of x
__device__ __half g_x0l[(size_t)BB * TT * IN0];
__device__ __half g_w0 [2][NG][IN0];                 // fp16 w_ih0
__device__ __half g_whh[2][2][NG][HH];               // fp16 [layer][dir]
__device__ __half g_hh[2][2][2][BB][HH];             // [layer][parity][dir][b][j]
__device__ __half g_hl[2][2][2][BB][HH];
__device__ unsigned g_garr[2][16];
__device__ unsigned g_ggen[2][16];

__global__ void zero_kernel()
{
    int tid = blockIdx.x * blockDim.x + threadIdx.x;
    int stride = gridDim.x * blockDim.x;
    const int nh = 2 * 2 * 2 * BB * HH / 2;   // uint count per array
    for (int i = tid; i < nh; i += stride) {
        ((unsigned*)g_hh)[i] = 0u;
        ((unsigned*)g_hl)[i] = 0u;
    }
    if (tid < 32) {
        ((unsigned*)g_garr)[tid] = 0u;
        ((unsigned*)g_ggen)[tid] = 0u;
    }
}

__device__ __forceinline__ float sigf(float x) { return 1.f / (1.f + __expf(-x)); }
__device__ __forceinline__ float tanhf_fast(float x) { return 2.f / (1.f + __expf(-2.f * x)) - 1.f; }

// ======================= helpers =======================
__device__ __forceinline__ uint32_t smem_u32(const void* p) {
    uint32_t a;
    asm("{ .reg .u64 t; cvta.to.shared.u64 t, %1; cvt.u32.u64 %0, t; }" : "=r"(a) : "l"(p));
    return a;
}
#define CP_ASYNC16(dst, src) \
    asm volatile("cp.async.cg.shared.global [%0], [%1], 16;" :: "r"(dst), "l"(src) : "memory")
#define CP_COMMIT() asm volatile("cp.async.commit_group;" ::: "memory")
#define CP_WAIT1()  asm volatile("cp.async.wait_group 1;" ::: "memory")
#define CP_WAIT0()  asm volatile("cp.async.wait_group 0;" ::: "memory")
#define LDMATRIX_X4(r0, r1, r2, r3, addr) \
    asm volatile("ldmatrix.sync.aligned.m8n8.x4.shared.b16 {%0,%1,%2,%3}, [%4];" \
                 : "=r"(r0), "=r"(r1), "=r"(r2), "=r"(r3) : "r"(addr))
#define MMA_F16(c0, c1, c2, c3, a0, a1, a2, a3, b0, b1) \
    asm volatile("mma.sync.aligned.m16n8k16.row.col.f32.f16.f16.f32 " \
                 "{%0,%1,%2,%3}, {%4,%5,%6,%7}, {%8,%9}, {%0,%1,%2,%3};" \
                 : "+f"(c0), "+f"(c1), "+f"(c2), "+f"(c3) \
                 : "r"(a0), "r"(a1), "r"(a2), "r"(a3), "r"(b0), "r"(b1))

// ---------------- per-group (8-block) barrier ----------------
__device__ __forceinline__ void group_sync(unsigned* arr, unsigned* gen)
{
    __syncthreads();
    if (threadIdx.x == 0) {
        __threadfence();
        unsigned g = *(volatile unsigned*)gen;
        if (atomicAdd(arr, 1u) == 7u) {
            atomicExch(arr, 0u);
            __threadfence();
            atomicAdd(gen, 1u);
        } else {
            while (*(volatile unsigned*)gen == g) { __nanosleep(32); }
        }
        __threadfence();
    }
    __syncthreads();
}

// ======================= conversion kernels =======================
__global__ void split_half_kernel(const float* __restrict__ src,
                                  __half* __restrict__ dh,
                                  __half* __restrict__ dl, int n)
{
    int i = blockIdx.x * blockDim.x + threadIdx.x;
    int stride = gridDim.x * blockDim.x;
    for (; i < n; i += stride) {
        float v = src[i];
        __half h = __float2half_rn(v);
        dh[i] = h;
        dl[i] = __float2half_rn(v - __half2float(h));
    }
}

__global__ void convh_kernel(const float* __restrict__ src, __half* __restrict__ dst, int n)
{
    int i = blockIdx.x * blockDim.x + threadIdx.x;
    int stride = gridDim.x * blockDim.x;
    for (; i < n; i += stride)
        dst[i] = __float2half_rn(src[i]);
}

// ======================= tensorized persistent LSTM layer (fp16 2-pass) ===========
// KIN = 16 (layer 0) or 0 (layer 1). Block: 256 thr (8 warps: 2m x 4gate).
// Tile: 64 batch rows x 32 h-cols x 4 gates. W fp16 resident in smem; A = h split hi/lo.
template<int KIN>
__global__ void __launch_bounds__(256, 1) lstm_seq_tc(
    const float* __restrict__ bias_f, const float* __restrict__ bias_b)
{
    constexpr int LAYER = (KIN == 16) ? 0 : 1;
    constexpr int K     = KIN + HH;          // 272 / 256
    constexpr int KS    = K / 16;            // 17 / 16
    constexpr int SEGW  = K / 8;             // 34 / 32
    constexpr int XSEG  = KIN / 8;           // 2 / 0
    constexpr int ROWB  = (K + 8) * 2;       // 560 / 528

    extern __shared__ char smem[];
    const uint32_t sA_h = smem_u32(smem);
    const uint32_t sA_l = sA_h + 64 * ROWB;
    const uint32_t sW   = sA_l + 64 * ROWB;  // single fp16 W plane, 128 rows
    float* Gs = (float*)smem;                // aliases A planes
    __shared__ float bias_s[128];

    const int tid = threadIdx.x;
    const int wid = tid >> 5, lid = tid & 31;
    const int warp_m = wid >> 2, warp_n = wid & 3;
    const int bx = blockIdx.x;
    const int n_idx = bx & 7, m_idx = (bx >> 3) & 7, dir = bx >> 6;
    const int n0 = n_idx * 32, m0 = m_idx * 64;
    unsigned* barr = &g_garr[LAYER][dir * 8 + m_idx];
    unsigned* bgen = &g_ggen[LAYER][dir * 8 + m_idx];

    if (LAYER == 0 && tid < 128)
        bias_s[tid] = (dir ? bias_b : bias_f)[(tid >> 5) * 256 + n0 + (tid & 31)];

    // ---- preload W tile (single fp16 plane) ----
    {
        const __half* wh = &g_whh[LAYER][dir][0][0];
        for (int s = tid; s < 128 * SEGW; s += 256) {
            int r = s / SEGW, seg = s % SEGW;
            int n = (r >> 5) * 256 + n0 + (r & 31);
            uint32_t dst = (uint32_t)(r * ROWB + seg * 16);
            if (KIN == 16 && seg < XSEG) {
                CP_ASYNC16(sW + dst, (const char*)&g_w0[dir][n][seg * 8]);
            } else {
                int hs = seg - XSEG;
                CP_ASYNC16(sW + dst, (const char*)&wh[n * HH + hs * 8]);
            }
        }
        CP_COMMIT(); CP_WAIT0();
        __syncthreads();
    }

    float cstate[8];
#pragma unroll
    for (int e = 0; e < 8; e++) cstate[e] = 0.f;

    const int a_row  = lid & 15;
    const int a_kof2 = (lid >> 4) * 16;
    const int b_g    = lid >> 3;
    const int b_row  = (b_g >> 1) * 8 + (lid & 7);
    const int b_kof2 = (b_g & 1) * 16;

    for (int t = 0; t < TT; t++) {
        const int tt  = dir ? (TT - 1 - t) : t;
        const int par = t & 1;
        const __half* hph = &g_hh[LAYER][par][dir][0][0];
        const __half* hpl = &g_hl[LAYER][par][dir][0][0];

        // ---- load A tile: [x_t(16) |] h_prev(256), hi & lo planes ----
        for (int s = tid; s < 64 * SEGW; s += 256) {
            int r = s / SEGW, seg = s % SEGW;
            int b = m0 + r;
            uint32_t dst = (uint32_t)(r * ROWB + seg * 16);
            if (KIN == 16 && seg < XSEG) {
                size_t xo = ((size_t)b * TT + tt) * IN0 + seg * 8;
                CP_ASYNC16(sA_h + dst, (const char*)(g_x0h + xo));
                CP_ASYNC16(sA_l + dst, (const char*)(g_x0l + xo));
            } else {
                int hs = seg - XSEG;
                CP_ASYNC16(sA_h + dst, (const char*)&hph[b * HH + hs * 8]);
                CP_ASYNC16(sA_l + dst, (const char*)&hpl[b * HH + hs * 8]);
            }
        }
        CP_COMMIT(); CP_WAIT0();
        __syncthreads();

        float c[2][4][4];
#pragma unroll
        for (int mt = 0; mt < 2; mt++)
#pragma unroll
            for (int nt = 0; nt < 4; nt++)
#pragma unroll
                for (int r = 0; r < 4; r++) c[mt][nt][r] = 0.f;

#pragma unroll
        for (int ks = 0; ks < KS; ks++) {
            const int kb = ks * 32;
            uint32_t aH[2][4], aL[2][4], bW[2][4];
#pragma unroll
            for (int mt = 0; mt < 2; mt++) {
                uint32_t off = (uint32_t)((warp_m * 32 + mt * 16 + a_row) * ROWB + kb + a_kof2);
                LDMATRIX_X4(aH[mt][0], aH[mt][1], aH[mt][2], aH[mt][3], sA_h + off);
                LDMATRIX_X4(aL[mt][0], aL[mt][1], aL[mt][2], aL[mt][3], sA_l + off);
            }
#pragma unroll
            for (int bt = 0; bt < 2; bt++) {
                uint32_t off = (uint32_t)((warp_n * 32 + bt * 16 + b_row) * ROWB + kb + b_kof2);
                LDMATRIX_X4(bW[bt][0], bW[bt][1], bW[bt][2], bW[bt][3], sW + off);
            }
#pragma unroll
            for (int mt = 0; mt < 2; mt++)
#pragma unroll
                for (int nt = 0; nt < 4; nt++) {
                    int bt = nt >> 1, sub = (nt & 1) * 2;
                    MMA_F16(c[mt][nt][0], c[mt][nt][1], c[mt][nt][2], c[mt][nt][3],
                            aH[mt][0], aH[mt][1], aH[mt][2], aH[mt][3],
                            bW[bt][sub], bW[bt][sub + 1]);
                    MMA_F16(c[mt][nt][0], c[mt][nt][1], c[mt][nt][2], c[mt][nt][3],
                            aL[mt][0], aL[mt][1], aL[mt][2], aL[mt][3],
                            bW[bt][sub], bW[bt][sub + 1]);
                }
        }
        __syncthreads();   // ldmatrix reads done before Gs overwrites A planes

#pragma unroll
        for (int mt = 0; mt < 2; mt++)
#pragma unroll
            for (int nt = 0; nt < 4; nt++) {
                int row = warp_m * 32 + mt * 16 + (lid >> 2);
                int col = warp_n * 32 + nt * 8 + (lid & 3) * 2;
                Gs[row * 132 + col]           = c[mt][nt][0];
                Gs[row * 132 + col + 1]       = c[mt][nt][1];
                Gs[(row + 8) * 132 + col]     = c[mt][nt][2];
                Gs[(row + 8) * 132 + col + 1] = c[mt][nt][3];
            }
        __syncthreads();

        __half* hnh = &g_hh[LAYER][par ^ 1][dir][0][0];
        __half* hnl = &g_hl[LAYER][par ^ 1][dir][0][0];
#pragma unroll
        for (int e = 0; e < 8; e++) {
            int p = tid + 256 * e;
            int row = p >> 5, hc = p & 31;
            int b = m0 + row;
            float gi = Gs[row * 132 + hc];
            float gf = Gs[row * 132 + 32 + hc];
            float gg = Gs[row * 132 + 64 + hc];
            float go = Gs[row * 132 + 96 + hc];
            if (LAYER == 0) {
                gi += bias_s[hc];
                gf += bias_s[32 + hc];
                gg += bias_s[64 + hc];
                go += bias_s[96 + hc];
            } else {
                const float* gx = &g_gx1[(((size_t)dir * TT + tt) * BB + b) * NG + n0 + hc];
                gi += gx[0];
                gf += gx[256];
                gg += gx[512];
                go += gx[768];
            }
            float cc = sigf(gf) * cstate[e] + sigf(gi) * tanhf_fast(gg);
            cstate[e] = cc;
            float h = sigf(go) * tanhf_fast(cc);
            __half hi = __float2half_rn(h);
            __half lo = __float2half_rn(h - __half2float(hi));
            size_t ho = (size_t)b * HH + n0 + hc;
            hnh[ho] = hi;
            hnl[ho] = lo;
            if (LAYER == 0) {
                size_t xo = ((size_t)b * TT + tt) * IN1 + dir * HH + n0 + hc;
                g_x1h[xo] = hi;
                g_x1l[xo] = lo;
            }
        }
        group_sync(barr, bgen);
    }
}

// ======================= layer-1 input pre-GEMM: fp16 2-pass, occ 2 ======
#define PG_PAD    40
#define PG_HBYTES (128 * PG_PAD * 2)               // 10240 per plane
#define PG_STAGE  (3 * PG_HBYTES)                  // 30720 (Ah, Al, Wh)
#define PG_SMEM   (2 * PG_STAGE)                   // 61440 -> 2 CTAs/SM

__device__ __forceinline__ void pg_load_stage(
    uint32_t sbase,
    const __half* Ah, const __half* Al, const __half* Wh,
    int k0, int tid)
{
#pragma unroll
    for (int i = 0; i < 2; i++) {
        int chunk = tid + 256 * i;          // 512 chunks: 128 rows x 4 segs
        int row = chunk >> 2, seg = chunk & 3;
        uint32_t doff = (uint32_t)(row * (PG_PAD * 2) + seg * 16);
        CP_ASYNC16(sbase + doff,                 (const char*)(Ah + (size_t)row * IN1 + k0) + seg * 16);
        CP_ASYNC16(sbase + PG_HBYTES + doff,     (const char*)(Al + (size_t)row * IN1 + k0) + seg * 16);
        CP_ASYNC16(sbase + 2 * PG_HBYTES + doff, (const char*)(Wh + (size_t)row * IN1 + k0) + seg * 16);
    }
}

__global__ void __launch_bounds__(256, 2) pregemm_mma(
    const float* __restrict__ b1f, const float* __restrict__ b1b)
{
    extern __shared__ char smem[];
    __shared__ float bias_s[128];
    const uint32_t s0 = smem_u32(smem);
    const int tid = threadIdx.x;
    const int wid = tid >> 5, lid = tid & 31;
    const int warp_m = wid >> 2, warp_n = wid & 3;

    const int dir   = blockIdx.x >> 3;
    const int ntile = blockIdx.x & 7;
    const int mtile = blockIdx.y;

    const float* bsrc = dir ? b1b : b1f;
    if (tid < 128) bias_s[tid] = bsrc[ntile * 128 + tid];

    const __half* Ah = g_x1h + (size_t)mtile * 128 * IN1;
    const __half* Al = g_x1l + (size_t)mtile * 128 * IN1;
    const __half* Wh = &g_w1[dir][ntile * 128][0];

    float c[4][4][4];
#pragma unroll
    for (int mt = 0; mt < 4; mt++)
#pragma unroll
        for (int nt = 0; nt < 4; nt++)
#pragma unroll
            for (int r = 0; r < 4; r++) c[mt][nt][r] = 0.f;

    pg_load_stage(s0,            Ah, Al, Wh, 0,  tid); CP_COMMIT();
    pg_load_stage(s0 + PG_STAGE, Ah, Al, Wh, 32, tid); CP_COMMIT();

    const int a_row = (lid & 15);
    const int a_kof = (lid >> 4) * 8;
    const int b_g   = lid >> 3;
    const int b_row = (b_g >> 1) * 8 + (lid & 7);
    const int b_kof = (b_g & 1) * 8;

    for (int ci = 0; ci < 16; ci++) {
        if (ci == 15) CP_WAIT0(); else CP_WAIT1();
        __syncthreads();

        const uint32_t sb = s0 + (ci & 1) * PG_STAGE;
        const uint32_t sA = sb;
        const uint32_t sW = sb + 2 * PG_HBYTES;

#pragma unroll
        for (int ks = 0; ks < 32; ks += 16) {
            uint32_t aH[4][4], aL[4][4], bW[2][4];
#pragma unroll
            for (int mt = 0; mt < 4; mt++) {
                int row = warp_m * 64 + mt * 16 + a_row;
                uint32_t off = (uint32_t)(row * (PG_PAD * 2) + (ks + a_kof) * 2);
                LDMATRIX_X4(aH[mt][0], aH[mt][1], aH[mt][2], aH[mt][3], sA + off);
                LDMATRIX_X4(aL[mt][0], aL[mt][1], aL[mt][2], aL[mt][3], sA + PG_HBYTES + off);
            }
#pragma unroll
            for (int bt = 0; bt < 2; bt++) {
                int row = warp_n * 32 + bt * 16 + b_row;
                uint32_t off = (uint32_t)(row * (PG_PAD * 2) + (ks + b_kof) * 2);
                LDMATRIX_X4(bW[bt][0], bW[bt][1], bW[bt][2], bW[bt][3], sW + off);
            }
#pragma unroll
            for (int mt = 0; mt < 4; mt++)
#pragma unroll
                for (int nt = 0; nt < 4; nt++) {
                    int bt = nt >> 1, sub = (nt & 1) * 2;
                    MMA_F16(c[mt][nt][0], c[mt][nt][1], c[mt][nt][2], c[mt][nt][3],
                            aH[mt][0], aH[mt][1], aH[mt][2], aH[mt][3],
                            bW[bt][sub], bW[bt][sub + 1]);
                    MMA_F16(c[mt][nt][0], c[mt][nt][1], c[mt][nt][2], c[mt][nt][3],
                            aL[mt][0], aL[mt][1], aL[mt][2], aL[mt][3],
                            bW[bt][sub], bW[bt][sub + 1]);
                }
        }
        __syncthreads();
        if (ci + 2 < 16) {
            pg_load_stage(s0 + (ci & 1) * PG_STAGE, Ah, Al, Wh, (ci + 2) * 32, tid);
            CP_COMMIT();
        }
    }

#pragma unroll
    for (int mt = 0; mt < 4; mt++) {
#pragma unroll
        for (int rh = 0; rh < 2; rh++) {
            int row = warp_m * 64 + mt * 16 + (lid >> 2) + rh * 8;
            size_t R = (size_t)mtile * 128 + row;
            int b = (int)(R >> 9), t = (int)(R & 511);
            float* dst = g_gx1 + (((size_t)dir * TT + t) * BB + b) * NG + ntile * 128;
#pragma unroll
            for (int nt = 0; nt < 4; nt++) {
                int col = warp_n * 32 + nt * 8 + (lid & 3) * 2;
                float2 v;
                v.x = c[mt][nt][rh * 2 + 0] + bias_s[col];
                v.y = c[mt][nt][rh * 2 + 1] + bias_s[col + 1];
                *(float2*)(dst + col) = v;
            }
        }
    }
}

// ======================= final projection =======================
__global__ void fc_kernel(const float* __restrict__ fcw, const float* __restrict__ fcb,
                          float* __restrict__ out)
{
    int b = blockIdx.x;
    int l = threadIdx.x;   // 64 threads
    __shared__ float hs[2 * HH];
    for (int j = threadIdx.x; j < 2 * HH; j += blockDim.x) {
        int d = j >> 8, jj = j & 255;
        hs[j] = __half2float(g_hh[1][0][d][b][jj]) + __half2float(g_hl[1][0][d][b][jj]);
    }
    __syncthreads();
    float s = fcb[l];
#pragma unroll 8
    for (int j = 0; j < 2 * HH; j++)
        s = fmaf(hs[j], fcw[l * (2 * HH) + j], s);
    out[b * LOUT + l] = s;
}

// ---------------- launch ----------------
extern "C" void kernel_launch(void* const* d_in, const int* in_sizes, int n_in,
                              void* d_out, int out_size)
{
    const float* x     = (const float*)d_in[0];
    const float* wih0f = (const float*)d_in[1];
    const float* whh0f = (const float*)d_in[2];
    const float* b0f   = (const float*)d_in[3];
    const float* wih0b = (const float*)d_in[4];
    const float* whh0b = (const float*)d_in[5];
    const float* b0b   = (const float*)d_in[6];
    const float* wih1f = (const float*)d_in[7];
    const float* whh1f = (const float*)d_in[8];
    const float* b1f   = (const float*)d_in[9];
    const float* wih1b = (const float*)d_in[10];
    const float* whh1b = (const float*)d_in[11];
    const float* b1b   = (const float*)d_in[12];
    const float* fcw   = (const float*)d_in[13];
    const float* fcb   = (const float*)d_in[14];
    float* out = (float*)d_out;

    const int SM0 = 256 * ((IN0 + HH + 8) * 2);   // 143360
    const int SM1 = 256 * ((HH + 8) * 2);         // 135168
    cudaFuncSetAttribute(lstm_seq_tc<16>, cudaFuncAttributeMaxDynamicSharedMemorySize, SM0);
    cudaFuncSetAttribute(lstm_seq_tc<0>,  cudaFuncAttributeMaxDynamicSharedMemorySize, SM1);
    cudaFuncSetAttribute(pregemm_mma, cudaFuncAttributeMaxDynamicSharedMemorySize, PG_SMEM);

    void *a_x0h, *a_x0l, *a_w0, *a_whh, *a_w1;
    cudaGetSymbolAddress(&a_x0h, g_x0h);
    cudaGetSymbolAddress(&a_x0l, g_x0l);
    cudaGetSymbolAddress(&a_w0, g_w0);
    cudaGetSymbolAddress(&a_whh, g_whh);
    cudaGetSymbolAddress(&a_w1, g_w1);
    __half* p_x0h = (__half*)a_x0h;
    __half* p_x0l = (__half*)a_x0l;
    __half* p_w0  = (__half*)a_w0;
    __half* p_whh = (__half*)a_whh;
    __half* p_w1  = (__half*)a_w1;

    zero_kernel<<<128, 256>>>();
    split_half_kernel<<<512, 256>>>(x, p_x0h, p_x0l, BB * TT * IN0);
    convh_kernel<<<32, 256>>>(wih0f, p_w0, NG * IN0);
    convh_kernel<<<32, 256>>>(wih0b, p_w0 + NG * IN0, NG * IN0);
    convh_kernel<<<256, 256>>>(whh0f, p_whh + 0 * NG * HH, NG * HH);
    convh_kernel<<<256, 256>>>(whh0b, p_whh + 1 * NG * HH, NG * HH);
    convh_kernel<<<256, 256>>>(whh1f, p_whh + 2 * NG * HH, NG * HH);
    convh_kernel<<<256, 256>>>(whh1b, p_whh + 3 * NG * HH, NG * HH);
    convh_kernel<<<512, 256>>>(wih1f, p_w1, NG * IN1);
    convh_kernel<<<512, 256>>>(wih1b, p_w1 + NG * IN1, NG * IN1);

    lstm_seq_tc<16><<<128, 256, SM0>>>(b0f, b0b);

    dim3 gt(16, 2048, 1);
    pregemm_mma<<<gt, 256, PG_SMEM>>>(b1f, b1b);

    lstm_seq_tc<0><<<128, 256, SM1>>>(nullptr, nullptr);

    fc_kernel<<<BB, LOUT>>>(fcw, fcb, out);
}

// round 11
// speedup vs baseline: 4.2277x; 1.3659x over previous
#include <cuda_runtime.h>
#include <cuda_fp16.h>
#include <cstdint>
#include <math.h>

// Problem dims
#define BB   512
#define TT   512
#define IN0  16
#define HH   256
#define NG   1024          // 4*H
#define IN1  (2 * HH)      // 512
#define LOUT 64

// ---------------- device scratch (static, no allocations) ----------------
__device__ float g_gx1 [(size_t)2 * TT * BB * NG];   // layer-1 input-GEMM precompute (+bias)
__device__ __half g_x1h[(size_t)BB * TT * IN1];      // fp16 x1 (layer-0 output), single plane
__device__ __half g_w1 [2][NG][IN1];                 // fp16 w_ih1
__device__ __half g_x0h[(size_t)BB * TT * IN0];      // split-fp16 of x
__device__ __half g_x0l[(size_t)BB * TT * IN0];
__device__ __half g_w0 [2][NG][IN0];                 // fp16 w_ih0
__device__ __half g_whh[2][2][NG][HH];               // fp16 [layer][dir]
__device__ __half g_hh[2][2][2][BB][HH];             // [layer][parity][dir][b][j]
__device__ __half g_hl[2][2][2][BB][HH];
__device__ unsigned g_garr[2][16];
__device__ unsigned g_ggen[2][16];

__global__ void zero_kernel()
{
    int tid = blockIdx.x * blockDim.x + threadIdx.x;
    int stride = gridDim.x * blockDim.x;
    const int nh = 2 * 2 * 2 * BB * HH / 2;   // uint count per array
    for (int i = tid; i < nh; i += stride) {
        ((unsigned*)g_hh)[i] = 0u;
        ((unsigned*)g_hl)[i] = 0u;
    }
    if (tid < 32) {
        ((unsigned*)g_garr)[tid] = 0u;
        ((unsigned*)g_ggen)[tid] = 0u;
    }
}

__device__ __forceinline__ float sigf(float x) { return 1.f / (1.f + __expf(-x)); }
__device__ __forceinline__ float tanhf_fast(float x) { return 2.f / (1.f + __expf(-2.f * x)) - 1.f; }

// ======================= helpers =======================
__device__ __forceinline__ uint32_t smem_u32(const void* p) {
    uint32_t a;
    asm("{ .reg .u64 t; cvta.to.shared.u64 t, %1; cvt.u32.u64 %0, t; }" : "=r"(a) : "l"(p));
    return a;
}
#define CP_ASYNC16(dst, src) \
    asm volatile("cp.async.cg.shared.global [%0], [%1], 16;" :: "r"(dst), "l"(src) : "memory")
#define CP_COMMIT() asm volatile("cp.async.commit_group;" ::: "memory")
#define CP_WAIT1()  asm volatile("cp.async.wait_group 1;" ::: "memory")
#define CP_WAIT0()  asm volatile("cp.async.wait_group 0;" ::: "memory")
#define LDMATRIX_X4(r0, r1, r2, r3, addr) \
    asm volatile("ldmatrix.sync.aligned.m8n8.x4.shared.b16 {%0,%1,%2,%3}, [%4];" \
                 : "=r"(r0), "=r"(r1), "=r"(r2), "=r"(r3) : "r"(addr))
#define MMA_F16(c0, c1, c2, c3, a0, a1, a2, a3, b0, b1) \
    asm volatile("mma.sync.aligned.m16n8k16.row.col.f32.f16.f16.f32 " \
                 "{%0,%1,%2,%3}, {%4,%5,%6,%7}, {%8,%9}, {%0,%1,%2,%3};" \
                 : "+f"(c0), "+f"(c1), "+f"(c2), "+f"(c3) \
                 : "r"(a0), "r"(a1), "r"(a2), "r"(a3), "r"(b0), "r"(b1))

// ---------------- per-group (8-block) barrier ----------------
// Release fence on the arrive side only: all cross-block steady-state reads
// go through cp.async.cg (L2-direct), so no acquire-side L1 invalidate needed.
__device__ __forceinline__ void group_sync(unsigned* arr, unsigned* gen)
{
    __syncthreads();
    if (threadIdx.x == 0) {
        __threadfence();
        unsigned g = *(volatile unsigned*)gen;
        if (atomicAdd(arr, 1u) == 7u) {
            atomicExch(arr, 0u);
            __threadfence();
            atomicAdd(gen, 1u);
        } else {
            while (*(volatile unsigned*)gen == g) { __nanosleep(32); }
        }
    }
    __syncthreads();
}

// ======================= conversion kernels =======================
__global__ void split_half_kernel(const float* __restrict__ src,
                                  __half* __restrict__ dh,
                                  __half* __restrict__ dl, int n)
{
    int i = blockIdx.x * blockDim.x + threadIdx.x;
    int stride = gridDim.x * blockDim.x;
    for (; i < n; i += stride) {
        float v = src[i];
        __half h = __float2half_rn(v);
        dh[i] = h;
        dl[i] = __float2half_rn(v - __half2float(h));
    }
}

__global__ void convh_kernel(const float* __restrict__ src, __half* __restrict__ dst, int n)
{
    int i = blockIdx.x * blockDim.x + threadIdx.x;
    int stride = gridDim.x * blockDim.x;
    for (; i < n; i += stride)
        dst[i] = __float2half_rn(src[i]);
}

// ======================= tensorized persistent LSTM layer (fp16 2-pass on A) ======
// KIN = 16 (layer 0) or 0 (layer 1). Block: 256 thr (8 warps: 2m x 4gate).
// Tile: 64 batch rows x 32 h-cols x 4 gates. W fp16 resident in smem; A = h split hi/lo.
// Layer 1: gx1 tile prefetched into smem, overlapped with MMA.
template<int KIN>
__global__ void __launch_bounds__(256, 1) lstm_seq_tc(
    const float* __restrict__ bias_f, const float* __restrict__ bias_b)
{
    constexpr int LAYER = (KIN == 16) ? 0 : 1;
    constexpr int K     = KIN + HH;          // 272 / 256
    constexpr int KS    = K / 16;            // 17 / 16
    constexpr int SEGW  = K / 8;             // 34 / 32
    constexpr int XSEG  = KIN / 8;           // 2 / 0
    constexpr int ROWB  = (K + 8) * 2;       // 560 / 528

    extern __shared__ char smem[];
    const uint32_t sA_h = smem_u32(smem);
    const uint32_t sA_l = sA_h + 64 * ROWB;
    const uint32_t sW   = sA_l + 64 * ROWB;  // single fp16 W plane, 128 rows
    const uint32_t sGx  = sW + 128 * ROWB;   // layer 1 only: 64 x 128 fp32
    float* Gs   = (float*)smem;              // aliases A planes
    float* GxS  = (float*)(smem + 256 * ROWB);
    __shared__ float bias_s[128];

    const int tid = threadIdx.x;
    const int wid = tid >> 5, lid = tid & 31;
    const int warp_m = wid >> 2, warp_n = wid & 3;
    const int bx = blockIdx.x;
    const int n_idx = bx & 7, m_idx = (bx >> 3) & 7, dir = bx >> 6;
    const int n0 = n_idx * 32, m0 = m_idx * 64;
    unsigned* barr = &g_garr[LAYER][dir * 8 + m_idx];
    unsigned* bgen = &g_ggen[LAYER][dir * 8 + m_idx];

    if (LAYER == 0 && tid < 128)
        bias_s[tid] = (dir ? bias_b : bias_f)[(tid >> 5) * 256 + n0 + (tid & 31)];

    // ---- preload W tile (single fp16 plane) ----
    {
        const __half* wh = &g_whh[LAYER][dir][0][0];
        for (int s = tid; s < 128 * SEGW; s += 256) {
            int r = s / SEGW, seg = s % SEGW;
            int n = (r >> 5) * 256 + n0 + (r & 31);
            uint32_t dst = (uint32_t)(r * ROWB + seg * 16);
            if (KIN == 16 && seg < XSEG) {
                CP_ASYNC16(sW + dst, (const char*)&g_w0[dir][n][seg * 8]);
            } else {
                int hs = seg - XSEG;
                CP_ASYNC16(sW + dst, (const char*)&wh[n * HH + hs * 8]);
            }
        }
        CP_COMMIT(); CP_WAIT0();
        __syncthreads();
    }

    float cstate[8];
#pragma unroll
    for (int e = 0; e < 8; e++) cstate[e] = 0.f;

    const int a_row  = lid & 15;
    const int a_kof2 = (lid >> 4) * 16;
    const int b_g    = lid >> 3;
    const int b_row  = (b_g >> 1) * 8 + (lid & 7);
    const int b_kof2 = (b_g & 1) * 16;

    for (int t = 0; t < TT; t++) {
        const int tt  = dir ? (TT - 1 - t) : t;
        const int par = t & 1;
        const __half* hph = &g_hh[LAYER][par][dir][0][0];
        const __half* hpl = &g_hl[LAYER][par][dir][0][0];

        // ---- load A tile: [x_t(16) |] h_prev(256), hi & lo planes ----
        for (int s = tid; s < 64 * SEGW; s += 256) {
            int r = s / SEGW, seg = s % SEGW;
            int b = m0 + r;
            uint32_t dst = (uint32_t)(r * ROWB + seg * 16);
            if (KIN == 16 && seg < XSEG) {
                size_t xo = ((size_t)b * TT + tt) * IN0 + seg * 8;
                CP_ASYNC16(sA_h + dst, (const char*)(g_x0h + xo));
                CP_ASYNC16(sA_l + dst, (const char*)(g_x0l + xo));
            } else {
                int hs = seg - XSEG;
                CP_ASYNC16(sA_h + dst, (const char*)&hph[b * HH + hs * 8]);
                CP_ASYNC16(sA_l + dst, (const char*)&hpl[b * HH + hs * 8]);
            }
        }
        CP_COMMIT();

        if (LAYER == 1) {
            // prefetch gx1 tile (64 rows x 4 gates x 32 cols fp32), overlapped with MMA
            const float* gxb = g_gx1 + (((size_t)dir * TT + tt) * BB + m0) * NG + n0;
#pragma unroll
            for (int i = 0; i < 8; i++) {
                int ch = tid + 256 * i;            // 0..2047
                int row = ch >> 5;
                int sub = ch & 31;                 // gate(2b) x seg(3b)
                int gate = sub >> 3, seg = sub & 7;
                const char* src = (const char*)(gxb + (size_t)row * NG + gate * 256) + seg * 16;
                CP_ASYNC16(sGx + (uint32_t)(row * 512 + gate * 128 + seg * 16), src);
            }
            CP_COMMIT();
            CP_WAIT1();      // A-tile complete; gx group still in flight
        } else {
            CP_WAIT0();
        }
        __syncthreads();

        float c[2][4][4];
#pragma unroll
        for (int mt = 0; mt < 2; mt++)
#pragma unroll
            for (int nt = 0; nt < 4; nt++)
#pragma unroll
                for (int r = 0; r < 4; r++) c[mt][nt][r] = 0.f;

#pragma unroll
        for (int ks = 0; ks < KS; ks++) {
            const int kb = ks * 32;
            uint32_t aH[2][4], aL[2][4], bW[2][4];
#pragma unroll
            for (int mt = 0; mt < 2; mt++) {
                uint32_t off = (uint32_t)((warp_m * 32 + mt * 16 + a_row) * ROWB + kb + a_kof2);
                LDMATRIX_X4(aH[mt][0], aH[mt][1], aH[mt][2], aH[mt][3], sA_h + off);
                LDMATRIX_X4(aL[mt][0], aL[mt][1], aL[mt][2], aL[mt][3], sA_l + off);
            }
#pragma unroll
            for (int bt = 0; bt < 2; bt++) {
                uint32_t off = (uint32_t)((warp_n * 32 + bt * 16 + b_row) * ROWB + kb + b_kof2);
                LDMATRIX_X4(bW[bt][0], bW[bt][1], bW[bt][2], bW[bt][3], sW + off);
            }
#pragma unroll
            for (int mt = 0; mt < 2; mt++)
#pragma unroll
                for (int nt = 0; nt < 4; nt++) {
                    int bt = nt >> 1, sub = (nt & 1) * 2;
                    MMA_F16(c[mt][nt][0], c[mt][nt][1], c[mt][nt][2], c[mt][nt][3],
                            aH[mt][0], aH[mt][1], aH[mt][2], aH[mt][3],
                            bW[bt][sub], bW[bt][sub + 1]);
                    MMA_F16(c[mt][nt][0], c[mt][nt][1], c[mt][nt][2], c[mt][nt][3],
                            aL[mt][0], aL[mt][1], aL[mt][2], aL[mt][3],
                            bW[bt][sub], bW[bt][sub + 1]);
                }
        }
        if (LAYER == 1) CP_WAIT0();   // gx tile landed (overlapped with MMA)
        __syncthreads();              // ldmatrix reads done before Gs overwrites A planes

#pragma unroll
        for (int mt = 0; mt < 2; mt++)
#pragma unroll
            for (int nt = 0; nt < 4; nt++) {
                int row = warp_m * 32 + mt * 16 + (lid >> 2);
                int col = warp_n * 32 + nt * 8 + (lid & 3) * 2;
                Gs[row * 132 + col]           = c[mt][nt][0];
                Gs[row * 132 + col + 1]       = c[mt][nt][1];
                Gs[(row + 8) * 132 + col]     = c[mt][nt][2];
                Gs[(row + 8) * 132 + col + 1] = c[mt][nt][3];
            }
        __syncthreads();

        __half* hnh = &g_hh[LAYER][par ^ 1][dir][0][0];
        __half* hnl = &g_hl[LAYER][par ^ 1][dir][0][0];
#pragma unroll
        for (int e = 0; e < 8; e++) {
            int p = tid + 256 * e;
            int row = p >> 5, hc = p & 31;
            int b = m0 + row;
            float gi = Gs[row * 132 + hc];
            float gf = Gs[row * 132 + 32 + hc];
            float gg = Gs[row * 132 + 64 + hc];
            float go = Gs[row * 132 + 96 + hc];
            if (LAYER == 0) {
                gi += bias_s[hc];
                gf += bias_s[32 + hc];
                gg += bias_s[64 + hc];
                go += bias_s[96 + hc];
            } else {
                gi += GxS[row * 128 + hc];
                gf += GxS[row * 128 + 32 + hc];
                gg += GxS[row * 128 + 64 + hc];
                go += GxS[row * 128 + 96 + hc];
            }
            float cc = sigf(gf) * cstate[e] + sigf(gi) * tanhf_fast(gg);
            cstate[e] = cc;
            float h = sigf(go) * tanhf_fast(cc);
            __half hi = __float2half_rn(h);
            __half lo = __float2half_rn(h - __half2float(hi));
            size_t ho = (size_t)b * HH + n0 + hc;
            hnh[ho] = hi;
            hnl[ho] = lo;
            if (LAYER == 0)
                g_x1h[((size_t)b * TT + tt) * IN1 + dir * HH + n0 + hc] = hi;
        }
        group_sync(barr, bgen);
    }
}

// ======================= layer-1 input pre-GEMM: fp16 single-pass, occ 2 ======
#define PG_PAD    40
#define PG_HBYTES (128 * PG_PAD * 2)               // 10240 per plane
#define PG_STAGE  (2 * PG_HBYTES)                  // 20480 (Ah, Wh)
#define PG_SMEM   (2 * PG_STAGE)                   // 40960 -> 2 CTAs/SM easily

__device__ __forceinline__ void pg_load_stage(
    uint32_t sbase, const __half* Ah, const __half* Wh, int k0, int tid)
{
#pragma unroll
    for (int i = 0; i < 2; i++) {
        int chunk = tid + 256 * i;          // 512 chunks: 128 rows x 4 segs
        int row = chunk >> 2, seg = chunk & 3;
        uint32_t doff = (uint32_t)(row * (PG_PAD * 2) + seg * 16);
        CP_ASYNC16(sbase + doff,             (const char*)(Ah + (size_t)row * IN1 + k0) + seg * 16);
        CP_ASYNC16(sbase + PG_HBYTES + doff, (const char*)(Wh + (size_t)row * IN1 + k0) + seg * 16);
    }
}

__global__ void __launch_bounds__(256, 2) pregemm_mma(
    const float* __restrict__ b1f, const float* __restrict__ b1b)
{
    extern __shared__ char smem[];
    __shared__ float bias_s[128];
    const uint32_t s0 = smem_u32(smem);
    const int tid = threadIdx.x;
    const int wid = tid >> 5, lid = tid & 31;
    const int warp_m = wid >> 2, warp_n = wid & 3;

    const int dir   = blockIdx.x >> 3;
    const int ntile = blockIdx.x & 7;
    const int mtile = blockIdx.y;

    const float* bsrc = dir ? b1b : b1f;
    if (tid < 128) bias_s[tid] = bsrc[ntile * 128 + tid];

    const __half* Ah = g_x1h + (size_t)mtile * 128 * IN1;
    const __half* Wh = &g_w1[dir][ntile * 128][0];

    float c[4][4][4];
#pragma unroll
    for (int mt = 0; mt < 4; mt++)
#pragma unroll
        for (int nt = 0; nt < 4; nt++)
#pragma unroll
            for (int r = 0; r < 4; r++) c[mt][nt][r] = 0.f;

    pg_load_stage(s0,            Ah, Wh, 0,  tid); CP_COMMIT();
    pg_load_stage(s0 + PG_STAGE, Ah, Wh, 32, tid); CP_COMMIT();

    const int a_row = (lid & 15);
    const int a_kof = (lid >> 4) * 8;
    const int b_g   = lid >> 3;
    const int b_row = (b_g >> 1) * 8 + (lid & 7);
    const int b_kof = (b_g & 1) * 8;

    for (int ci = 0; ci < 16; ci++) {
        if (ci == 15) CP_WAIT0(); else CP_WAIT1();
        __syncthreads();

        const uint32_t sb = s0 + (ci & 1) * PG_STAGE;
        const uint32_t sA = sb;
        const uint32_t sW = sb + PG_HBYTES;

#pragma unroll
        for (int ks = 0; ks < 32; ks += 16) {
            uint32_t aH[4][4], bW[2][4];
#pragma unroll
            for (int mt = 0; mt < 4; mt++) {
                int row = warp_m * 64 + mt * 16 + a_row;
                uint32_t off = (uint32_t)(row * (PG_PAD * 2) + (ks + a_kof) * 2);
                LDMATRIX_X4(aH[mt][0], aH[mt][1], aH[mt][2], aH[mt][3], sA + off);
            }
#pragma unroll
            for (int bt = 0; bt < 2; bt++) {
                int row = warp_n * 32 + bt * 16 + b_row;
                uint32_t off = (uint32_t)(row * (PG_PAD * 2) + (ks + b_kof) * 2);
                LDMATRIX_X4(bW[bt][0], bW[bt][1], bW[bt][2], bW[bt][3], sW + off);
            }
#pragma unroll
            for (int mt = 0; mt < 4; mt++)
#pragma unroll
                for (int nt = 0; nt < 4; nt++) {
                    int bt = nt >> 1, sub = (nt & 1) * 2;
                    MMA_F16(c[mt][nt][0], c[mt][nt][1], c[mt][nt][2], c[mt][nt][3],
                            aH[mt][0], aH[mt][1], aH[mt][2], aH[mt][3],
                            bW[bt][sub], bW[bt][sub + 1]);
                }
        }
        __syncthreads();
        if (ci + 2 < 16) {
            pg_load_stage(s0 + (ci & 1) * PG_STAGE, Ah, Wh, (ci + 2) * 32, tid);
            CP_COMMIT();
        }
    }

#pragma unroll
    for (int mt = 0; mt < 4; mt++) {
#pragma unroll
        for (int rh = 0; rh < 2; rh++) {
            int row = warp_m * 64 + mt * 16 + (lid >> 2) + rh * 8;
            size_t R = (size_t)mtile * 128 + row;
            int b = (int)(R >> 9), t = (int)(R & 511);
            float* dst = g_gx1 + (((size_t)dir * TT + t) * BB + b) * NG + ntile * 128;
#pragma unroll
            for (int nt = 0; nt < 4; nt++) {
                int col = warp_n * 32 + nt * 8 + (lid & 3) * 2;
                float2 v;
                v.x = c[mt][nt][rh * 2 + 0] + bias_s[col];
                v.y = c[mt][nt][rh * 2 + 1] + bias_s[col + 1];
                *(float2*)(dst + col) = v;
            }
        }
    }
}

// ======================= final projection =======================
__global__ void fc_kernel(const float* __restrict__ fcw, const float* __restrict__ fcb,
                          float* __restrict__ out)
{
    int b = blockIdx.x;
    int l = threadIdx.x;   // 64 threads
    __shared__ float hs[2 * HH];
    for (int j = threadIdx.x; j < 2 * HH; j += blockDim.x) {
        int d = j >> 8, jj = j & 255;
        hs[j] = __half2float(g_hh[1][0][d][b][jj]) + __half2float(g_hl[1][0][d][b][jj]);
    }
    __syncthreads();
    float s = fcb[l];
#pragma unroll 8
    for (int j = 0; j < 2 * HH; j++)
        s = fmaf(hs[j], fcw[l * (2 * HH) + j], s);
    out[b * LOUT + l] = s;
}

// ---------------- launch ----------------
extern "C" void kernel_launch(void* const* d_in, const int* in_sizes, int n_in,
                              void* d_out, int out_size)
{
    const float* x     = (const float*)d_in[0];
    const float* wih0f = (const float*)d_in[1];
    const float* whh0f = (const float*)d_in[2];
    const float* b0f   = (const float*)d_in[3];
    const float* wih0b = (const float*)d_in[4];
    const float* whh0b = (const float*)d_in[5];
    const float* b0b   = (const float*)d_in[6];
    const float* wih1f = (const float*)d_in[7];
    const float* whh1f = (const float*)d_in[8];
    const float* b1f   = (const float*)d_in[9];
    const float* wih1b = (const float*)d_in[10];
    const float* whh1b = (const float*)d_in[11];
    const float* b1b   = (const float*)d_in[12];
    const float* fcw   = (const float*)d_in[13];
    const float* fcb   = (const float*)d_in[14];
    float* out = (float*)d_out;

    const int SM0 = 256 * ((IN0 + HH + 8) * 2);              // 143360
    const int SM1 = 256 * ((HH + 8) * 2) + 64 * 128 * 4;     // 135168 + 32768 = 167936
    cudaFuncSetAttribute(lstm_seq_tc<16>, cudaFuncAttributeMaxDynamicSharedMemorySize, SM0);
    cudaFuncSetAttribute(lstm_seq_tc<0>,  cudaFuncAttributeMaxDynamicSharedMemorySize, SM1);
    cudaFuncSetAttribute(pregemm_mma, cudaFuncAttributeMaxDynamicSharedMemorySize, PG_SMEM);

    void *a_x0h, *a_x0l, *a_w0, *a_whh, *a_w1;
    cudaGetSymbolAddress(&a_x0h, g_x0h);
    cudaGetSymbolAddress(&a_x0l, g_x0l);
    cudaGetSymbolAddress(&a_w0, g_w0);
    cudaGetSymbolAddress(&a_whh, g_whh);
    cudaGetSymbolAddress(&a_w1, g_w1);
    __half* p_x0h = (__half*)a_x0h;
    __half* p_x0l = (__half*)a_x0l;
    __half* p_w0  = (__half*)a_w0;
    __half* p_whh = (__half*)a_whh;
    __half* p_w1  = (__half*)a_w1;

    zero_kernel<<<128, 256>>>();
    split_half_kernel<<<512, 256>>>(x, p_x0h, p_x0l, BB * TT * IN0);
    convh_kernel<<<32, 256>>>(wih0f, p_w0, NG * IN0);
    convh_kernel<<<32, 256>>>(wih0b, p_w0 + NG * IN0, NG * IN0);
    convh_kernel<<<256, 256>>>(whh0f, p_whh + 0 * NG * HH, NG * HH);
    convh_kernel<<<256, 256>>>(whh0b, p_whh + 1 * NG * HH, NG * HH);
    convh_kernel<<<256, 256>>>(whh1f, p_whh + 2 * NG * HH, NG * HH);
    convh_kernel<<<256, 256>>>(whh1b, p_whh + 3 * NG * HH, NG * HH);
    convh_kernel<<<512, 256>>>(wih1f, p_w1, NG * IN1);
    convh_kernel<<<512, 256>>>(wih1b, p_w1 + NG * IN1, NG * IN1);

    lstm_seq_tc<16><<<128, 256, SM0>>>(b0f, b0b);

    dim3 gt(16, 2048, 1);
    pregemm_mma<<<gt, 256, PG_SMEM>>>(b1f, b1b);

    lstm_seq_tc<0><<<128, 256, SM1>>>(nullptr, nullptr);

    fc_kernel<<<BB, LOUT>>>(fcw, fcb, out);
}

// round 12
// speedup vs baseline: 5.0028x; 1.1833x over previous
#include <cuda_runtime.h>
#include <cuda_fp16.h>
#include <cstdint>
#include <math.h>

// Problem dims
#define BB   512
#define TT   512
#define IN0  16
#define HH   256
#define NG   1024          // 4*H
#define IN1  (2 * HH)      // 512
#define LOUT 64

// ---------------- device scratch (static, no allocations) ----------------
__device__ float g_gx1 [(size_t)2 * TT * BB * NG];   // layer-1 input-GEMM precompute (+bias)
__device__ __half g_x1h[(size_t)BB * TT * IN1];      // fp16 x1 (layer-0 output)
__device__ __half g_w1 [2][NG][IN1];                 // fp16 w_ih1
__device__ __half g_x0h[(size_t)BB * TT * IN0];      // fp16 x
__device__ __half g_w0 [2][NG][IN0];                 // fp16 w_ih0
__device__ __half g_whh[2][2][NG][HH];               // fp16 [layer][dir]
__device__ __half g_hh[2][2][2][BB][HH];             // [layer][parity][dir][b][j]
__device__ unsigned g_garr[2][16];
__device__ unsigned g_ggen[2][16];

__global__ void zero_kernel()
{
    int tid = blockIdx.x * blockDim.x + threadIdx.x;
    int stride = gridDim.x * blockDim.x;
    const int nh = 2 * 2 * 2 * BB * HH / 2;   // uint count
    for (int i = tid; i < nh; i += stride)
        ((unsigned*)g_hh)[i] = 0u;
    if (tid < 32) {
        ((unsigned*)g_garr)[tid] = 0u;
        ((unsigned*)g_ggen)[tid] = 0u;
    }
}

__device__ __forceinline__ float sigf(float x) { return 1.f / (1.f + __expf(-x)); }
__device__ __forceinline__ float tanhf_fast(float x) { return 2.f / (1.f + __expf(-2.f * x)) - 1.f; }

// ======================= helpers =======================
__device__ __forceinline__ uint32_t smem_u32(const void* p) {
    uint32_t a;
    asm("{ .reg .u64 t; cvta.to.shared.u64 t, %1; cvt.u32.u64 %0, t; }" : "=r"(a) : "l"(p));
    return a;
}
#define CP_ASYNC16(dst, src) \
    asm volatile("cp.async.cg.shared.global [%0], [%1], 16;" :: "r"(dst), "l"(src) : "memory")
#define CP_COMMIT() asm volatile("cp.async.commit_group;" ::: "memory")
#define CP_WAIT1()  asm volatile("cp.async.wait_group 1;" ::: "memory")
#define CP_WAIT0()  asm volatile("cp.async.wait_group 0;" ::: "memory")
#define LDMATRIX_X4(r0, r1, r2, r3, addr) \
    asm volatile("ldmatrix.sync.aligned.m8n8.x4.shared.b16 {%0,%1,%2,%3}, [%4];" \
                 : "=r"(r0), "=r"(r1), "=r"(r2), "=r"(r3) : "r"(addr))
#define MMA_F16(c0, c1, c2, c3, a0, a1, a2, a3, b0, b1) \
    asm volatile("mma.sync.aligned.m16n8k16.row.col.f32.f16.f16.f32 " \
                 "{%0,%1,%2,%3}, {%4,%5,%6,%7}, {%8,%9}, {%0,%1,%2,%3};" \
                 : "+f"(c0), "+f"(c1), "+f"(c2), "+f"(c3) \
                 : "r"(a0), "r"(a1), "r"(a2), "r"(a3), "r"(b0), "r"(b1))

// ---------------- per-group (8-block) barrier ----------------
__device__ __forceinline__ void group_sync(unsigned* arr, unsigned* gen)
{
    __syncthreads();
    if (threadIdx.x == 0) {
        __threadfence();
        unsigned g = *(volatile unsigned*)gen;
        if (atomicAdd(arr, 1u) == 7u) {
            atomicExch(arr, 0u);
            __threadfence();
            atomicAdd(gen, 1u);
        } else {
            while (*(volatile unsigned*)gen == g) { __nanosleep(32); }
        }
    }
    __syncthreads();
}

// ======================= conversion kernel =======================
__global__ void convh_kernel(const float* __restrict__ src, __half* __restrict__ dst, int n)
{
    int i = blockIdx.x * blockDim.x + threadIdx.x;
    int stride = gridDim.x * blockDim.x;
    for (; i < n; i += stride)
        dst[i] = __float2half_rn(src[i]);
}

// ======================= tensorized persistent LSTM layer =======================
// Single-pass fp16 MMA; W-tile rows gate-interleaved so each thread's accumulators
// hold all 4 gates for its (row, col) pairs -> cell update fully in registers.
// Block: 256 thr (8 warps: 2m x 4n). Tile: 64 batch rows x 32 h-cols x 4 gates.
// Warp n-tile = 4 gates x 8 h-cols (nt = gate).
template<int KIN>
__global__ void __launch_bounds__(256, 1) lstm_seq_tc(
    const float* __restrict__ bias_f, const float* __restrict__ bias_b)
{
    constexpr int LAYER = (KIN == 16) ? 0 : 1;
    constexpr int K     = KIN + HH;          // 272 / 256
    constexpr int KS    = K / 16;            // 17 / 16
    constexpr int SEGW  = K / 8;             // 34 / 32
    constexpr int XSEG  = KIN / 8;           // 2 / 0
    constexpr int ROWB  = (K + 8) * 2;       // 560 / 528

    extern __shared__ char smem[];
    const uint32_t sA  = smem_u32(smem);
    const uint32_t sW  = sA + 64 * ROWB;
    const uint32_t sGx = sA + 192 * ROWB;    // layer 1 only: 64 x 128 fp32
    float* GxS = (float*)(smem + 192 * ROWB);
    __shared__ float bias_s[128];

    const int tid = threadIdx.x;
    const int wid = tid >> 5, lid = tid & 31;
    const int warp_m = wid >> 2, warp_n = wid & 3;
    const int bx = blockIdx.x;
    const int n_idx = bx & 7, m_idx = (bx >> 3) & 7, dir = bx >> 6;
    const int n0 = n_idx * 32, m0 = m_idx * 64;
    unsigned* barr = &g_garr[LAYER][dir * 8 + m_idx];
    unsigned* bgen = &g_ggen[LAYER][dir * 8 + m_idx];

    if (LAYER == 0 && tid < 128)
        bias_s[tid] = (dir ? bias_b : bias_f)[(tid >> 5) * 256 + n0 + (tid & 31)];

    // ---- preload W tile: row r -> gate=(r>>3)&3, hcol=(r>>5)*8+(r&7) ----
    {
        const __half* wh = &g_whh[LAYER][dir][0][0];
        for (int s = tid; s < 128 * SEGW; s += 256) {
            int r = s / SEGW, seg = s % SEGW;
            int n = ((r >> 3) & 3) * 256 + n0 + (r >> 5) * 8 + (r & 7);
            uint32_t dst = (uint32_t)(r * ROWB + seg * 16);
            if (KIN == 16 && seg < XSEG) {
                CP_ASYNC16(sW + dst, (const char*)&g_w0[dir][n][seg * 8]);
            } else {
                int hs = seg - XSEG;
                CP_ASYNC16(sW + dst, (const char*)&wh[n * HH + hs * 8]);
            }
        }
        CP_COMMIT(); CP_WAIT0();
        __syncthreads();
    }

    float cstate[8];
#pragma unroll
    for (int e = 0; e < 8; e++) cstate[e] = 0.f;

    const int a_row  = lid & 15;
    const int a_kof2 = (lid >> 4) * 16;
    const int b_g    = lid >> 3;
    const int b_row  = (b_g >> 1) * 8 + (lid & 7);
    const int b_kof2 = (b_g & 1) * 16;

    for (int t = 0; t < TT; t++) {
        const int tt  = dir ? (TT - 1 - t) : t;
        const int par = t & 1;
        const __half* hph = &g_hh[LAYER][par][dir][0][0];

        // ---- load A tile: [x_t(16) |] h_prev(256), single fp16 plane ----
        for (int s = tid; s < 64 * SEGW; s += 256) {
            int r = s / SEGW, seg = s % SEGW;
            int b = m0 + r;
            uint32_t dst = (uint32_t)(r * ROWB + seg * 16);
            if (KIN == 16 && seg < XSEG) {
                size_t xo = ((size_t)b * TT + tt) * IN0 + seg * 8;
                CP_ASYNC16(sA + dst, (const char*)(g_x0h + xo));
            } else {
                int hs = seg - XSEG;
                CP_ASYNC16(sA + dst, (const char*)&hph[b * HH + hs * 8]);
            }
        }
        CP_COMMIT();

        if (LAYER == 1) {
            // prefetch gx1 tile (64 rows x 4 gates x 32 cols fp32), overlapped with MMA
            const float* gxb = g_gx1 + (((size_t)dir * TT + tt) * BB + m0) * NG + n0;
#pragma unroll
            for (int i = 0; i < 8; i++) {
                int ch = tid + 256 * i;            // 0..2047
                int row = ch >> 5;
                int sub = ch & 31;
                int gate = sub >> 3, seg = sub & 7;
                const char* src = (const char*)(gxb + (size_t)row * NG + gate * 256) + seg * 16;
                CP_ASYNC16(sGx + (uint32_t)(row * 512 + gate * 128 + seg * 16), src);
            }
            CP_COMMIT();
            CP_WAIT1();      // A-tile complete; gx still in flight
        } else {
            CP_WAIT0();
        }
        __syncthreads();

        float c[2][4][4];
#pragma unroll
        for (int mt = 0; mt < 2; mt++)
#pragma unroll
            for (int nt = 0; nt < 4; nt++)
#pragma unroll
                for (int r = 0; r < 4; r++) c[mt][nt][r] = 0.f;

#pragma unroll
        for (int ks = 0; ks < KS; ks++) {
            const int kb = ks * 32;
            uint32_t aH[2][4], bW[2][4];
#pragma unroll
            for (int mt = 0; mt < 2; mt++) {
                uint32_t off = (uint32_t)((warp_m * 32 + mt * 16 + a_row) * ROWB + kb + a_kof2);
                LDMATRIX_X4(aH[mt][0], aH[mt][1], aH[mt][2], aH[mt][3], sA + off);
            }
#pragma unroll
            for (int bt = 0; bt < 2; bt++) {
                uint32_t off = (uint32_t)((warp_n * 32 + bt * 16 + b_row) * ROWB + kb + b_kof2);
                LDMATRIX_X4(bW[bt][0], bW[bt][1], bW[bt][2], bW[bt][3], sW + off);
            }
#pragma unroll
            for (int mt = 0; mt < 2; mt++)
#pragma unroll
                for (int nt = 0; nt < 4; nt++) {
                    int bt = nt >> 1, sub = (nt & 1) * 2;
                    MMA_F16(c[mt][nt][0], c[mt][nt][1], c[mt][nt][2], c[mt][nt][3],
                            aH[mt][0], aH[mt][1], aH[mt][2], aH[mt][3],
                            bW[bt][sub], bW[bt][sub + 1]);
                }
        }

        if (LAYER == 1) {
            CP_WAIT0();          // gx tile landed (overlapped with MMA)
            __syncthreads();     // make all threads' gx cp.asyncs visible
        }

        // ---- cell update entirely in registers: c[mt][gate][r] ----
        // nt(=gate) n8-groups: tile rows warp_n*32 + gate*8 + c  ->
        //   h col = n0 + warp_n*8 + (lid&3)*2 + cc,  row = warp_m*32+mt*16+(lid>>2)+rh*8
        __half* hnh = &g_hh[LAYER][par ^ 1][dir][0][0];
#pragma unroll
        for (int mt = 0; mt < 2; mt++) {
#pragma unroll
            for (int rh = 0; rh < 2; rh++) {
                int row  = warp_m * 32 + mt * 16 + (lid >> 2) + rh * 8;
                int colp = warp_n * 8 + (lid & 3) * 2;     // even col in [0,32)
                int b = m0 + row;
                float hv[2];
#pragma unroll
                for (int cc = 0; cc < 2; cc++) {
                    int r = rh * 2 + cc;
                    int e = mt * 4 + rh * 2 + cc;
                    float gi = c[mt][0][r];
                    float gf = c[mt][1][r];
                    float gg = c[mt][2][r];
                    float go = c[mt][3][r];
                    if (LAYER == 0) {
                        gi += bias_s[colp + cc];
                        gf += bias_s[32 + colp + cc];
                        gg += bias_s[64 + colp + cc];
                        go += bias_s[96 + colp + cc];
                    } else {
                        gi += GxS[row * 128 + colp + cc];
                        gf += GxS[row * 128 + 32 + colp + cc];
                        gg += GxS[row * 128 + 64 + colp + cc];
                        go += GxS[row * 128 + 96 + colp + cc];
                    }
                    float ccv = sigf(gf) * cstate[e] + sigf(gi) * tanhf_fast(gg);
                    cstate[e] = ccv;
                    hv[cc] = sigf(go) * tanhf_fast(ccv);
                }
                __half2 h2 = __floats2half2_rn(hv[0], hv[1]);
                *(__half2*)&hnh[(size_t)b * HH + n0 + colp] = h2;
                if (LAYER == 0)
                    *(__half2*)&g_x1h[((size_t)b * TT + tt) * IN1 + dir * HH + n0 + colp] = h2;
            }
        }
        group_sync(barr, bgen);
    }
}

// ======================= layer-1 input pre-GEMM: fp16 single-pass, occ 2 ======
#define PG_PAD    40
#define PG_HBYTES (128 * PG_PAD * 2)               // 10240 per plane
#define PG_STAGE  (2 * PG_HBYTES)                  // 20480 (Ah, Wh)
#define PG_SMEM   (2 * PG_STAGE)                   // 40960

__device__ __forceinline__ void pg_load_stage(
    uint32_t sbase, const __half* Ah, const __half* Wh, int k0, int tid)
{
#pragma unroll
    for (int i = 0; i < 2; i++) {
        int chunk = tid + 256 * i;
        int row = chunk >> 2, seg = chunk & 3;
        uint32_t doff = (uint32_t)(row * (PG_PAD * 2) + seg * 16);
        CP_ASYNC16(sbase + doff,             (const char*)(Ah + (size_t)row * IN1 + k0) + seg * 16);
        CP_ASYNC16(sbase + PG_HBYTES + doff, (const char*)(Wh + (size_t)row * IN1 + k0) + seg * 16);
    }
}

__global__ void __launch_bounds__(256, 2) pregemm_mma(
    const float* __restrict__ b1f, const float* __restrict__ b1b)
{
    extern __shared__ char smem[];
    __shared__ float bias_s[128];
    const uint32_t s0 = smem_u32(smem);
    const int tid = threadIdx.x;
    const int wid = tid >> 5, lid = tid & 31;
    const int warp_m = wid >> 2, warp_n = wid & 3;

    const int dir   = blockIdx.x >> 3;
    const int ntile = blockIdx.x & 7;
    const int mtile = blockIdx.y;

    const float* bsrc = dir ? b1b : b1f;
    if (tid < 128) bias_s[tid] = bsrc[ntile * 128 + tid];

    const __half* Ah = g_x1h + (size_t)mtile * 128 * IN1;
    const __half* Wh = &g_w1[dir][ntile * 128][0];

    float c[4][4][4];
#pragma unroll
    for (int mt = 0; mt < 4; mt++)
#pragma unroll
        for (int nt = 0; nt < 4; nt++)
#pragma unroll
            for (int r = 0; r < 4; r++) c[mt][nt][r] = 0.f;

    pg_load_stage(s0,            Ah, Wh, 0,  tid); CP_COMMIT();
    pg_load_stage(s0 + PG_STAGE, Ah, Wh, 32, tid); CP_COMMIT();

    const int a_row = (lid & 15);
    const int a_kof = (lid >> 4) * 8;
    const int b_g   = lid >> 3;
    const int b_row = (b_g >> 1) * 8 + (lid & 7);
    const int b_kof = (b_g & 1) * 8;

    for (int ci = 0; ci < 16; ci++) {
        if (ci == 15) CP_WAIT0(); else CP_WAIT1();
        __syncthreads();

        const uint32_t sb = s0 + (ci & 1) * PG_STAGE;
        const uint32_t sA = sb;
        const uint32_t sW = sb + PG_HBYTES;

#pragma unroll
        for (int ks = 0; ks < 32; ks += 16) {
            uint32_t aH[4][4], bW[2][4];
#pragma unroll
            for (int mt = 0; mt < 4; mt++) {
                int row = warp_m * 64 + mt * 16 + a_row;
                uint32_t off = (uint32_t)(row * (PG_PAD * 2) + (ks + a_kof) * 2);
                LDMATRIX_X4(aH[mt][0], aH[mt][1], aH[mt][2], aH[mt][3], sA + off);
            }
#pragma unroll
            for (int bt = 0; bt < 2; bt++) {
                int row = warp_n * 32 + bt * 16 + b_row;
                uint32_t off = (uint32_t)(row * (PG_PAD * 2) + (ks + b_kof) * 2);
                LDMATRIX_X4(bW[bt][0], bW[bt][1], bW[bt][2], bW[bt][3], sW + off);
            }
#pragma unroll
            for (int mt = 0; mt < 4; mt++)
#pragma unroll
                for (int nt = 0; nt < 4; nt++) {
                    int bt = nt >> 1, sub = (nt & 1) * 2;
                    MMA_F16(c[mt][nt][0], c[mt][nt][1], c[mt][nt][2], c[mt][nt][3],
                            aH[mt][0], aH[mt][1], aH[mt][2], aH[mt][3],
                            bW[bt][sub], bW[bt][sub + 1]);
                }
        }
        __syncthreads();
        if (ci + 2 < 16) {
            pg_load_stage(s0 + (ci & 1) * PG_STAGE, Ah, Wh, (ci + 2) * 32, tid);
            CP_COMMIT();
        }
    }

#pragma unroll
    for (int mt = 0; mt < 4; mt++) {
#pragma unroll
        for (int rh = 0; rh < 2; rh++) {
            int row = warp_m * 64 + mt * 16 + (lid >> 2) + rh * 8;
            size_t R = (size_t)mtile * 128 + row;
            int b = (int)(R >> 9), t = (int)(R & 511);
            float* dst = g_gx1 + (((size_t)dir * TT + t) * BB + b) * NG + ntile * 128;
#pragma unroll
            for (int nt = 0; nt < 4; nt++) {
                int col = warp_n * 32 + nt * 8 + (lid & 3) * 2;
                float2 v;
                v.x = c[mt][nt][rh * 2 + 0] + bias_s[col];
                v.y = c[mt][nt][rh * 2 + 1] + bias_s[col + 1];
                *(float2*)(dst + col) = v;
            }
        }
    }
}

// ======================= final projection =======================
__global__ void fc_kernel(const float* __restrict__ fcw, const float* __restrict__ fcb,
                          float* __restrict__ out)
{
    int b = blockIdx.x;
    int l = threadIdx.x;   // 64 threads
    __shared__ float hs[2 * HH];
    for (int j = threadIdx.x; j < 2 * HH; j += blockDim.x) {
        int d = j >> 8, jj = j & 255;
        hs[j] = __half2float(g_hh[1][0][d][b][jj]);
    }
    __syncthreads();
    float s = fcb[l];
#pragma unroll 8
    for (int j = 0; j < 2 * HH; j++)
        s = fmaf(hs[j], fcw[l * (2 * HH) + j], s);
    out[b * LOUT + l] = s;
}

// ---------------- launch ----------------
extern "C" void kernel_launch(void* const* d_in, const int* in_sizes, int n_in,
                              void* d_out, int out_size)
{
    const float* x     = (const float*)d_in[0];
    const float* wih0f = (const float*)d_in[1];
    const float* whh0f = (const float*)d_in[2];
    const float* b0f   = (const float*)d_in[3];
    const float* wih0b = (const float*)d_in[4];
    const float* whh0b = (const float*)d_in[5];
    const float* b0b   = (const float*)d_in[6];
    const float* wih1f = (const float*)d_in[7];
    const float* whh1f = (const float*)d_in[8];
    const float* b1f   = (const float*)d_in[9];
    const float* wih1b = (const float*)d_in[10];
    const float* whh1b = (const float*)d_in[11];
    const float* b1b   = (const float*)d_in[12];
    const float* fcw   = (const float*)d_in[13];
    const float* fcb   = (const float*)d_in[14];
    float* out = (float*)d_out;

    const int SM0 = 192 * ((IN0 + HH + 8) * 2);              // 107520
    const int SM1 = 192 * ((HH + 8) * 2) + 64 * 128 * 4;     // 101376 + 32768 = 134144
    cudaFuncSetAttribute(lstm_seq_tc<16>, cudaFuncAttributeMaxDynamicSharedMemorySize, SM0);
    cudaFuncSetAttribute(lstm_seq_tc<0>,  cudaFuncAttributeMaxDynamicSharedMemorySize, SM1);
    cudaFuncSetAttribute(pregemm_mma, cudaFuncAttributeMaxDynamicSharedMemorySize, PG_SMEM);

    void *a_x0h, *a_w0, *a_whh, *a_w1;
    cudaGetSymbolAddress(&a_x0h, g_x0h);
    cudaGetSymbolAddress(&a_w0, g_w0);
    cudaGetSymbolAddress(&a_whh, g_whh);
    cudaGetSymbolAddress(&a_w1, g_w1);
    __half* p_x0h = (__half*)a_x0h;
    __half* p_w0  = (__half*)a_w0;
    __half* p_whh = (__half*)a_whh;
    __half* p_w1  = (__half*)a_w1;

    zero_kernel<<<128, 256>>>();
    convh_kernel<<<512, 256>>>(x, p_x0h, BB * TT * IN0);
    convh_kernel<<<32, 256>>>(wih0f, p_w0, NG * IN0);
    convh_kernel<<<32, 256>>>(wih0b, p_w0 + NG * IN0, NG * IN0);
    convh_kernel<<<256, 256>>>(whh0f, p_whh + 0 * NG * HH, NG * HH);
    convh_kernel<<<256, 256>>>(whh0b, p_whh + 1 * NG * HH, NG * HH);
    convh_kernel<<<256, 256>>>(whh1f, p_whh + 2 * NG * HH, NG * HH);
    convh_kernel<<<256, 256>>>(whh1b, p_whh + 3 * NG * HH, NG * HH);
    convh_kernel<<<512, 256>>>(wih1f, p_w1, NG * IN1);
    convh_kernel<<<512, 256>>>(wih1b, p_w1 + NG * IN1, NG * IN1);

    lstm_seq_tc<16><<<128, 256, SM0>>>(b0f, b0b);

    dim3 gt(16, 2048, 1);
    pregemm_mma<<<gt, 256, PG_SMEM>>>(b1f, b1b);

    lstm_seq_tc<0><<<128, 256, SM1>>>(nullptr, nullptr);

    fc_kernel<<<BB, LOUT>>>(fcw, fcb, out);
}

// round 15
// speedup vs baseline: 5.8375x; 1.1669x over previous
#include <cuda_runtime.h>
#include <cuda_fp16.h>
#include <cstdint>
#include <math.h>

// Problem dims
#define BB   512
#define TT   512
#define IN0  16
#define HH   256
#define NG   1024          // 4*H
#define IN1  (2 * HH)      // 512
#define LOUT 64

// ---------------- device scratch (static, no allocations) ----------------
__device__ float g_gx1 [(size_t)2 * TT * BB * NG];   // layer-1 input-GEMM precompute (+bias)
__device__ __half g_x1h[(size_t)BB * TT * IN1];      // fp16 x1 (layer-0 output)
__device__ __half g_w1 [2][NG][IN1];                 // fp16 w_ih1
__device__ __half g_x0h[(size_t)BB * TT * IN0];      // fp16 x
__device__ __half g_w0 [2][NG][IN0];                 // fp16 w_ih0
__device__ __half g_whh[2][2][NG][HH];               // fp16 [layer][dir]
__device__ __half g_hh[2][2][2][BB][HH];             // [layer][parity][dir][b][j]
__device__ unsigned g_garr[2][32];
__device__ unsigned g_ggen[2][32];

__global__ void zero_kernel()
{
    int tid = blockIdx.x * blockDim.x + threadIdx.x;
    int stride = gridDim.x * blockDim.x;
    const int nh = 2 * 2 * 2 * BB * HH / 2;   // uint count
    for (int i = tid; i < nh; i += stride)
        ((unsigned*)g_hh)[i] = 0u;
    if (tid < 64) {
        ((unsigned*)g_garr)[tid] = 0u;
        ((unsigned*)g_ggen)[tid] = 0u;
    }
}

__device__ __forceinline__ float sigf(float x) { return 1.f / (1.f + __expf(-x)); }
__device__ __forceinline__ float tanhf_fast(float x) { return 2.f / (1.f + __expf(-2.f * x)) - 1.f; }

// ======================= helpers =======================
__device__ __forceinline__ uint32_t smem_u32(const void* p) {
    uint32_t a;
    asm("{ .reg .u64 t; cvta.to.shared.u64 t, %1; cvt.u32.u64 %0, t; }" : "=r"(a) : "l"(p));
    return a;
}
#define CP_ASYNC16(dst, src) \
    asm volatile("cp.async.cg.shared.global [%0], [%1], 16;" :: "r"(dst), "l"(src) : "memory")
#define CP_COMMIT() asm volatile("cp.async.commit_group;" ::: "memory")
#define CP_WAIT1()  asm volatile("cp.async.wait_group 1;" ::: "memory")
#define CP_WAIT0()  asm volatile("cp.async.wait_group 0;" ::: "memory")
#define LDMATRIX_X4(r0, r1, r2, r3, addr) \
    asm volatile("ldmatrix.sync.aligned.m8n8.x4.shared.b16 {%0,%1,%2,%3}, [%4];" \
                 : "=r"(r0), "=r"(r1), "=r"(r2), "=r"(r3) : "r"(addr))
#define MMA_F16(c0, c1, c2, c3, a0, a1, a2, a3, b0, b1) \
    asm volatile("mma.sync.aligned.m16n8k16.row.col.f32.f16.f16.f32 " \
                 "{%0,%1,%2,%3}, {%4,%5,%6,%7}, {%8,%9}, {%0,%1,%2,%3};" \
                 : "+f"(c0), "+f"(c1), "+f"(c2), "+f"(c3) \
                 : "r"(a0), "r"(a1), "r"(a2), "r"(a3), "r"(b0), "r"(b1))

// ---------------- per-group (8-block) barrier ----------------
__device__ __forceinline__ void group_sync(unsigned* arr, unsigned* gen)
{
    __syncthreads();
    if (threadIdx.x == 0) {
        __threadfence();
        unsigned g = *(volatile unsigned*)gen;
        if (atomicAdd(arr, 1u) == 7u) {
            atomicExch(arr, 0u);
            __threadfence();
            atomicAdd(gen, 1u);
        } else {
            while (*(volatile unsigned*)gen == g) { __nanosleep(32); }
        }
    }
    __syncthreads();
}

// ======================= conversion kernel =======================
__global__ void convh_kernel(const float* __restrict__ src, __half* __restrict__ dst, int n)
{
    int i = blockIdx.x * blockDim.x + threadIdx.x;
    int stride = gridDim.x * blockDim.x;
    for (; i < n; i += stride)
        dst[i] = __float2half_rn(src[i]);
}

// ======================= tensorized persistent LSTM layer =======================
// 256 blocks: 16 m-tiles (32 rows) x 8 n-tiles (32 h-cols x 4 gates) x 2 dirs,
// __launch_bounds__(256,2) -> 2 CTAs/SM, 296 slots >= 256 (co-residency guaranteed).
// Single-pass fp16 MMA; W rows gate-interleaved -> cell update fully in registers.
// Barrier group = 8 n-blocks sharing (dir, m_idx).
template<int KIN>
__global__ void __launch_bounds__(256, 2) lstm_seq_tc(
    const float* __restrict__ bias_f, const float* __restrict__ bias_b)
{
    constexpr int LAYER = (KIN == 16) ? 0 : 1;
    constexpr int K     = KIN + HH;          // 272 / 256
    constexpr int KS    = K / 16;            // 17 / 16
    constexpr int SEGW  = K / 8;             // 34 / 32
    constexpr int XSEG  = KIN / 8;           // 2 / 0
    constexpr int ROWB  = (K + 8) * 2;       // 560 / 528

    extern __shared__ char smem[];
    const uint32_t sA  = smem_u32(smem);
    const uint32_t sW  = sA + 32 * ROWB;
    const uint32_t sGx = sA + 160 * ROWB;    // layer 1 only: 32 x 128 fp32
    float* GxS = (float*)(smem + 160 * ROWB);
    __shared__ float bias_s[128];

    const int tid = threadIdx.x;
    const int wid = tid >> 5, lid = tid & 31;
    const int warp_m = wid >> 2, warp_n = wid & 3;   // warp_m 0..1 (16 rows each)
    const int bx = blockIdx.x;
    const int n_idx = bx & 7, m_idx = (bx >> 3) & 15, dir = bx >> 7;
    const int n0 = n_idx * 32, m0 = m_idx * 32;
    unsigned* barr = &g_garr[LAYER][dir * 16 + m_idx];
    unsigned* bgen = &g_ggen[LAYER][dir * 16 + m_idx];

    if (LAYER == 0 && tid < 128)
        bias_s[tid] = (dir ? bias_b : bias_f)[(tid >> 5) * 256 + n0 + (tid & 31)];

    // ---- preload W tile: row r -> gate=(r>>3)&3, hcol=(r>>5)*8+(r&7) ----
    {
        const __half* wh = &g_whh[LAYER][dir][0][0];
        for (int s = tid; s < 128 * SEGW; s += 256) {
            int r = s / SEGW, seg = s % SEGW;
            int n = ((r >> 3) & 3) * 256 + n0 + (r >> 5) * 8 + (r & 7);
            uint32_t dst = (uint32_t)(r * ROWB + seg * 16);
            if (KIN == 16 && seg < XSEG) {
                CP_ASYNC16(sW + dst, (const char*)&g_w0[dir][n][seg * 8]);
            } else {
                int hs = seg - XSEG;
                CP_ASYNC16(sW + dst, (const char*)&wh[n * HH + hs * 8]);
            }
        }
        CP_COMMIT(); CP_WAIT0();
        __syncthreads();
    }

    float cstate[4];
#pragma unroll
    for (int e = 0; e < 4; e++) cstate[e] = 0.f;

    const int a_row  = lid & 15;
    const int a_kof2 = (lid >> 4) * 16;
    const int b_g    = lid >> 3;
    const int b_row  = (b_g >> 1) * 8 + (lid & 7);
    const int b_kof2 = (b_g & 1) * 16;

    for (int t = 0; t < TT; t++) {
        const int tt  = dir ? (TT - 1 - t) : t;
        const int par = t & 1;
        const __half* hph = &g_hh[LAYER][par][dir][0][0];

        // ---- load A tile: [x_t(16) |] h_prev(256), 32 rows ----
        for (int s = tid; s < 32 * SEGW; s += 256) {
            int r = s / SEGW, seg = s % SEGW;
            int b = m0 + r;
            uint32_t dst = (uint32_t)(r * ROWB + seg * 16);
            if (KIN == 16 && seg < XSEG) {
                size_t xo = ((size_t)b * TT + tt) * IN0 + seg * 8;
                CP_ASYNC16(sA + dst, (const char*)(g_x0h + xo));
            } else {
                int hs = seg - XSEG;
                CP_ASYNC16(sA + dst, (const char*)&hph[b * HH + hs * 8]);
            }
        }
        CP_COMMIT();

        if (LAYER == 1) {
            // prefetch gx1 tile (32 rows x 4 gates x 32 cols fp32), overlapped with MMA
            const float* gxb = g_gx1 + (((size_t)dir * TT + tt) * BB + m0) * NG + n0;
#pragma unroll
            for (int i = 0; i < 4; i++) {
                int ch = tid + 256 * i;            // 0..1023
                int row = ch >> 5;
                int sub = ch & 31;
                int gate = sub >> 3, seg = sub & 7;
                const char* src = (const char*)(gxb + (size_t)row * NG + gate * 256) + seg * 16;
                CP_ASYNC16(sGx + (uint32_t)(row * 512 + gate * 128 + seg * 16), src);
            }
            CP_COMMIT();
            CP_WAIT1();      // A-tile complete; gx still in flight
        } else {
            CP_WAIT0();
        }
        __syncthreads();

        float c[4][4];
#pragma unroll
        for (int nt = 0; nt < 4; nt++)
#pragma unroll
            for (int r = 0; r < 4; r++) c[nt][r] = 0.f;

#pragma unroll
        for (int ks = 0; ks < KS; ks++) {
            const int kb = ks * 32;
            uint32_t aH[4], bW[2][4];
            {
                uint32_t off = (uint32_t)((warp_m * 16 + a_row) * ROWB + kb + a_kof2);
                LDMATRIX_X4(aH[0], aH[1], aH[2], aH[3], sA + off);
            }
#pragma unroll
            for (int bt = 0; bt < 2; bt++) {
                uint32_t off = (uint32_t)((warp_n * 32 + bt * 16 + b_row) * ROWB + kb + b_kof2);
                LDMATRIX_X4(bW[bt][0], bW[bt][1], bW[bt][2], bW[bt][3], sW + off);
            }
#pragma unroll
            for (int nt = 0; nt < 4; nt++) {
                int bt = nt >> 1, sub = (nt & 1) * 2;
                MMA_F16(c[nt][0], c[nt][1], c[nt][2], c[nt][3],
                        aH[0], aH[1], aH[2], aH[3],
                        bW[bt][sub], bW[bt][sub + 1]);
            }
        }

        if (LAYER == 1) {
            CP_WAIT0();          // gx tile landed (overlapped with MMA)
            __syncthreads();     // make all threads' gx cp.asyncs visible
        }

        // ---- cell update entirely in registers: c[gate][r] ----
        __half* hnh = &g_hh[LAYER][par ^ 1][dir][0][0];
#pragma unroll
        for (int rh = 0; rh < 2; rh++) {
            int row  = warp_m * 16 + (lid >> 2) + rh * 8;
            int colp = warp_n * 8 + (lid & 3) * 2;     // even col in [0,32)
            int b = m0 + row;
            float hv[2];
#pragma unroll
            for (int cc = 0; cc < 2; cc++) {
                int r = rh * 2 + cc;
                int e = rh * 2 + cc;
                float gi = c[0][r];
                float gf = c[1][r];
                float gg = c[2][r];
                float go = c[3][r];
                if (LAYER == 0) {
                    gi += bias_s[colp + cc];
                    gf += bias_s[32 + colp + cc];
                    gg += bias_s[64 + colp + cc];
                    go += bias_s[96 + colp + cc];
                } else {
                    gi += GxS[row * 128 + colp + cc];
                    gf += GxS[row * 128 + 32 + colp + cc];
                    gg += GxS[row * 128 + 64 + colp + cc];
                    go += GxS[row * 128 + 96 + colp + cc];
                }
                float ccv = sigf(gf) * cstate[e] + sigf(gi) * tanhf_fast(gg);
                cstate[e] = ccv;
                hv[cc] = sigf(go) * tanhf_fast(ccv);
            }
            __half2 h2 = __floats2half2_rn(hv[0], hv[1]);
            *(__half2*)&hnh[(size_t)b * HH + n0 + colp] = h2;
            if (LAYER == 0)
                *(__half2*)&g_x1h[((size_t)b * TT + tt) * IN1 + dir * HH + n0 + colp] = h2;
        }
        group_sync(barr, bgen);
    }
}

// ======================= layer-1 input pre-GEMM: fp16 single-pass, occ 2 ======
#define PG_PAD    40
#define PG_HBYTES (128 * PG_PAD * 2)               // 10240 per plane
#define PG_STAGE  (2 * PG_HBYTES)                  // 20480 (Ah, Wh)
#define PG_SMEM   (2 * PG_STAGE)                   // 40960

__device__ __forceinline__ void pg_load_stage(
    uint32_t sbase, const __half* Ah, const __half* Wh, int k0, int tid)
{
#pragma unroll
    for (int i = 0; i < 2; i++) {
        int chunk = tid + 256 * i;
        int row = chunk >> 2, seg = chunk & 3;
        uint32_t doff = (uint32_t)(row * (PG_PAD * 2) + seg * 16);
        CP_ASYNC16(sbase + doff,             (const char*)(Ah + (size_t)row * IN1 + k0) + seg * 16);
        CP_ASYNC16(sbase + PG_HBYTES + doff, (const char*)(Wh + (size_t)row * IN1 + k0) + seg * 16);
    }
}

__global__ void __launch_bounds__(256, 2) pregemm_mma(
    const float* __restrict__ b1f, const float* __restrict__ b1b)
{
    extern __shared__ char smem[];
    __shared__ float bias_s[128];
    const uint32_t s0 = smem_u32(smem);
    const int tid = threadIdx.x;
    const int wid = tid >> 5, lid = tid & 31;
    const int warp_m = wid >> 2, warp_n = wid & 3;

    const int dir   = blockIdx.x >> 3;
    const int ntile = blockIdx.x & 7;
    const int mtile = blockIdx.y;

    const float* bsrc = dir ? b1b : b1f;
    if (tid < 128) bias_s[tid] = bsrc[ntile * 128 + tid];

    const __half* Ah = g_x1h + (size_t)mtile * 128 * IN1;
    const __half* Wh = &g_w1[dir][ntile * 128][0];

    float c[4][4][4];
#pragma unroll
    for (int mt = 0; mt < 4; mt++)
#pragma unroll
        for (int nt = 0; nt < 4; nt++)
#pragma unroll
            for (int r = 0; r < 4; r++) c[mt][nt][r] = 0.f;

    pg_load_stage(s0,            Ah, Wh, 0,  tid); CP_COMMIT();
    pg_load_stage(s0 + PG_STAGE, Ah, Wh, 32, tid); CP_COMMIT();

    const int a_row = (lid & 15);
    const int a_kof = (lid >> 4) * 8;
    const int b_g   = lid >> 3;
    const int b_row = (b_g >> 1) * 8 + (lid & 7);
    const int b_kof = (b_g & 1) * 8;

    for (int ci = 0; ci < 16; ci++) {
        if (ci == 15) CP_WAIT0(); else CP_WAIT1();
        __syncthreads();

        const uint32_t sb = s0 + (ci & 1) * PG_STAGE;
        const uint32_t sA = sb;
        const uint32_t sW = sb + PG_HBYTES;

#pragma unroll
        for (int ks = 0; ks < 32; ks += 16) {
            uint32_t aH[4][4], bW[2][4];
#pragma unroll
            for (int mt = 0; mt < 4; mt++) {
                int row = warp_m * 64 + mt * 16 + a_row;
                uint32_t off = (uint32_t)(row * (PG_PAD * 2) + (ks + a_kof) * 2);
                LDMATRIX_X4(aH[mt][0], aH[mt][1], aH[mt][2], aH[mt][3], sA + off);
            }
#pragma unroll
            for (int bt = 0; bt < 2; bt++) {
                int row = warp_n * 32 + bt * 16 + b_row;
                uint32_t off = (uint32_t)(row * (PG_PAD * 2) + (ks + b_kof) * 2);
                LDMATRIX_X4(bW[bt][0], bW[bt][1], bW[bt][2], bW[bt][3], sW + off);
            }
#pragma unroll
            for (int mt = 0; mt < 4; mt++)
#pragma unroll
                for (int nt = 0; nt < 4; nt++) {
                    int bt = nt >> 1, sub = (nt & 1) * 2;
                    MMA_F16(c[mt][nt][0], c[mt][nt][1], c[mt][nt][2], c[mt][nt][3],
                            aH[mt][0], aH[mt][1], aH[mt][2], aH[mt][3],
                            bW[bt][sub], bW[bt][sub + 1]);
                }
        }
        __syncthreads();
        if (ci + 2 < 16) {
            pg_load_stage(s0 + (ci & 1) * PG_STAGE, Ah, Wh, (ci + 2) * 32, tid);
            CP_COMMIT();
        }
    }

#pragma unroll
    for (int mt = 0; mt < 4; mt++) {
#pragma unroll
        for (int rh = 0; rh < 2; rh++) {
            int row = warp_m * 64 + mt * 16 + (lid >> 2) + rh * 8;
            size_t R = (size_t)mtile * 128 + row;
            int b = (int)(R >> 9), t = (int)(R & 511);
            float* dst = g_gx1 + (((size_t)dir * TT + t) * BB + b) * NG + ntile * 128;
#pragma unroll
            for (int nt = 0; nt < 4; nt++) {
                int col = warp_n * 32 + nt * 8 + (lid & 3) * 2;
                float2 v;
                v.x = c[mt][nt][rh * 2 + 0] + bias_s[col];
                v.y = c[mt][nt][rh * 2 + 1] + bias_s[col + 1];
                *(float2*)(dst + col) = v;
            }
        }
    }
}

// ======================= final projection =======================
__global__ void fc_kernel(const float* __restrict__ fcw, const float* __restrict__ fcb,
                          float* __restrict__ out)
{
    int b = blockIdx.x;
    int l = threadIdx.x;   // 64 threads
    __shared__ float hs[2 * HH];
    for (int j = threadIdx.x; j < 2 * HH; j += blockDim.x) {
        int d = j >> 8, jj = j & 255;
        hs[j] = __half2float(g_hh[1][0][d][b][jj]);
    }
    __syncthreads();
    float s = fcb[l];
#pragma unroll 8
    for (int j = 0; j < 2 * HH; j++)
        s = fmaf(hs[j], fcw[l * (2 * HH) + j], s);
    out[b * LOUT + l] = s;
}

// ---------------- launch ----------------
extern "C" void kernel_launch(void* const* d_in, const int* in_sizes, int n_in,
                              void* d_out, int out_size)
{
    const float* x     = (const float*)d_in[0];
    const float* wih0f = (const float*)d_in[1];
    const float* whh0f = (const float*)d_in[2];
    const float* b0f   = (const float*)d_in[3];
    const float* wih0b = (const float*)d_in[4];
    const float* whh0b = (const float*)d_in[5];
    const float* b0b   = (const float*)d_in[6];
    const float* wih1f = (const float*)d_in[7];
    const float* whh1f = (const float*)d_in[8];
    const float* b1f   = (const float*)d_in[9];
    const float* wih1b = (const float*)d_in[10];
    const float* whh1b = (const float*)d_in[11];
    const float* b1b   = (const float*)d_in[12];
    const float* fcw   = (const float*)d_in[13];
    const float* fcb   = (const float*)d_in[14];
    float* out = (float*)d_out;

    const int SM0 = 160 * ((IN0 + HH + 8) * 2);              // 89600
    const int SM1 = 160 * ((HH + 8) * 2) + 32 * 128 * 4;     // 84480 + 16384 = 100864
    cudaFuncSetAttribute(lstm_seq_tc<16>, cudaFuncAttributeMaxDynamicSharedMemorySize, SM0);
    cudaFuncSetAttribute(lstm_seq_tc<0>,  cudaFuncAttributeMaxDynamicSharedMemorySize, SM1);
    cudaFuncSetAttribute(pregemm_mma, cudaFuncAttributeMaxDynamicSharedMemorySize, PG_SMEM);

    void *a_x0h, *a_w0, *a_whh, *a_w1;
    cudaGetSymbolAddress(&a_x0h, g_x0h);
    cudaGetSymbolAddress(&a_w0, g_w0);
    cudaGetSymbolAddress(&a_whh, g_whh);
    cudaGetSymbolAddress(&a_w1, g_w1);
    __half* p_x0h = (__half*)a_x0h;
    __half* p_w0  = (__half*)a_w0;
    __half* p_whh = (__half*)a_whh;
    __half* p_w1  = (__half*)a_w1;

    zero_kernel<<<128, 256>>>();
    convh_kernel<<<512, 256>>>(x, p_x0h, BB * TT * IN0);
    convh_kernel<<<32, 256>>>(wih0f, p_w0, NG * IN0);
    convh_kernel<<<32, 256>>>(wih0b, p_w0 + NG * IN0, NG * IN0);
    convh_kernel<<<256, 256>>>(whh0f, p_whh + 0 * NG * HH, NG * HH);
    convh_kernel<<<256, 256>>>(whh0b, p_whh + 1 * NG * HH, NG * HH);
    convh_kernel<<<256, 256>>>(whh1f, p_whh + 2 * NG * HH, NG * HH);
    convh_kernel<<<256, 256>>>(whh1b, p_whh + 3 * NG * HH, NG * HH);
    convh_kernel<<<512, 256>>>(wih1f, p_w1, NG * IN1);
    convh_kernel<<<512, 256>>>(wih1b, p_w1 + NG * IN1, NG * IN1);

    lstm_seq_tc<16><<<256, 256, SM0>>>(b0f, b0b);

    dim3 gt(16, 2048, 1);
    pregemm_mma<<<gt, 256, PG_SMEM>>>(b1f, b1b);

    lstm_seq_tc<0><<<256, 256, SM1>>>(nullptr, nullptr);

    fc_kernel<<<BB, LOUT>>>(fcw, fcb, out);
}